// round 13
// baseline (speedup 1.0000x reference)
#include <cuda_runtime.h>
#include <cuda_bf16.h>
#include <math.h>
#include <stdint.h>

#define N_NODES 50000
#define E_EDGES 500000
#define HDIM    128

// ---- scratch (device globals; no allocation in kernel_launch) ----
__device__ int   g_deg[N_NODES];          // zeroed at BSS init; re-zeroed by scan_deg each run
__device__ int   g_rowstart[N_NODES + 1];
__device__ int   g_cursor[N_NODES];
__device__ int   g_csr_src[E_EDGES];
__device__ float g_h1  [(size_t)N_NODES * HDIM];
__device__ float g_U   [(size_t)N_NODES * 256];
__device__ float g_xp1 [(size_t)N_NODES * HDIM];   // x @ Wr1^T
__device__ float g_xp2 [(size_t)N_NODES * HDIM];   // h1 @ Wr2^T
// pre-split operands (bf16 hi/lo)
__device__ __nv_bfloat16 g_aggh[(size_t)N_NODES * HDIM];
__device__ __nv_bfloat16 g_aggl[(size_t)N_NODES * HDIM];
__device__ __nv_bfloat16 g_h1h [(size_t)N_NODES * HDIM];
__device__ __nv_bfloat16 g_h1l [(size_t)N_NODES * HDIM];
// split weights bf16 hi/lo, [n][k] row-major:
// L1 [128][256] @0, L2 [128][256] @32768, W3a [128][128] @65536, W3b [128][128] @81920
__device__ __nv_bfloat16 g_Wh[98304];
__device__ __nv_bfloat16 g_Wlo[98304];

__device__ __forceinline__ uint32_t smem_u32(const void* p) {
    uint32_t a;
    asm("{ .reg .u64 t; cvta.to.shared.u64 t, %1; cvt.u32.u64 %0, t; }" : "=r"(a) : "l"(p));
    return a;
}
#define LDSM_X4(r0, r1, r2, r3, a) \
    asm volatile("ldmatrix.sync.aligned.m8n8.x4.shared.b16 {%0,%1,%2,%3}, [%4];" \
        : "=r"(r0), "=r"(r1), "=r"(r2), "=r"(r3) : "r"(a))
#define MMA_BF16(c, a, b0, b1) \
    asm volatile("mma.sync.aligned.m16n8k16.row.col.f32.bf16.bf16.f32 " \
        "{%0,%1,%2,%3}, {%4,%5,%6,%7}, {%8,%9}, {%0,%1,%2,%3};" \
        : "+f"((c)[0]), "+f"((c)[1]), "+f"((c)[2]), "+f"((c)[3]) \
        : "r"((a)[0]), "r"((a)[1]), "r"((a)[2]), "r"((a)[3]), "r"(b0), "r"(b1))
#define CP16(dst, src) \
    asm volatile("cp.async.ca.shared.global [%0], [%1], 16;" :: "r"(dst), "l"(src))
#define CP_COMMIT() asm volatile("cp.async.commit_group;" ::: "memory")
#define CP_WAIT1()  asm volatile("cp.async.wait_group 1;" ::: "memory")

__device__ __forceinline__ void split_bf16(float v, __nv_bfloat16& h, __nv_bfloat16& l) {
    h = __float2bfloat16(v);
    l = __float2bfloat16(v - __bfloat162float(h));
}
__device__ __forceinline__ uint32_t pack2(__nv_bfloat16 a, __nv_bfloat16 b) {
    return (uint32_t)__bfloat16_as_ushort(a) | ((uint32_t)__bfloat16_as_ushort(b) << 16);
}

// ---------------- fused: degree count + weight split ----------------
__global__ void countsplit_kernel(const int* __restrict__ dst, int E,
                                  const float* __restrict__ Wl1, const float* __restrict__ Wr1,
                                  const float* __restrict__ Wl2, const float* __restrict__ Wr2,
                                  const float* __restrict__ W3) {
    int i = blockIdx.x * blockDim.x + threadIdx.x;
    if (i < E) atomicAdd(&g_deg[dst[i]], 1);
    if (i < 98304) {
        float v;
        if (i < 32768) {
            int n = i >> 8, k = i & 255;
            v = (k < 128) ? Wl1[n * 128 + k] : Wr1[n * 128 + (k - 128)];
        } else if (i < 65536) {
            int j = i - 32768;
            int n = j >> 8, k = j & 255;
            v = (k < 128) ? Wl2[n * 128 + k] : Wr2[n * 128 + (k - 128)];
        } else {
            int j = i - 65536;
            int half = j >> 14;
            int jj = j & 16383;
            int n = jj >> 7, k = jj & 127;
            v = W3[n * 256 + half * 128 + k];
        }
        __nv_bfloat16 h, l;
        split_bf16(v, h, l);
        g_Wh[i]  = h;
        g_Wlo[i] = l;
    }
}

// scan + re-zero g_deg (keeps the zeroed invariant for the next graph replay)
__global__ void scan_deg_kernel(int E) {
    __shared__ int ssum[1024];
    int tid = threadIdx.x;
    const int chunk = (N_NODES + 1023) / 1024;
    int start = tid * chunk;
    int end = min(start + chunk, N_NODES);
    int s = 0;
    for (int i = start; i < end; i++) s += g_deg[i];
    ssum[tid] = s;
    __syncthreads();
    for (int d = 1; d < 1024; d <<= 1) {
        int v = (tid >= d) ? ssum[tid - d] : 0;
        __syncthreads();
        ssum[tid] += v;
        __syncthreads();
    }
    int run = ssum[tid] - s;
    for (int i = start; i < end; i++) {
        g_rowstart[i] = run;
        g_cursor[i]   = run;
        run += g_deg[i];
    }
    if (tid == 1023) g_rowstart[N_NODES] = E;
    for (int i = start; i < end; i++) g_deg[i] = 0;
}

__global__ void fill_csr_kernel(const int* __restrict__ src,
                                const int* __restrict__ dst, int E) {
    int i = blockIdx.x * blockDim.x + threadIdx.x;
    if (i < E) {
        int p = atomicAdd(&g_cursor[dst[i]], 1);
        g_csr_src[p] = src[i];
    }
}

// ---------------- mean aggregation: warp per node, MLP=8; writes split bf16 ----------------
__global__ void agg_mean_kernel(const float* __restrict__ xin, int use_h1) {
    int gw   = (blockIdx.x * blockDim.x + threadIdx.x) >> 5;
    int lane = threadIdx.x & 31;
    if (gw >= N_NODES) return;
    const float* in = use_h1 ? g_h1 : xin;
    int s = g_rowstart[gw];
    int e = g_rowstart[gw + 1];
    float4 a0 = make_float4(0.f, 0.f, 0.f, 0.f);
    float4 a1 = make_float4(0.f, 0.f, 0.f, 0.f);
    float4 a2 = make_float4(0.f, 0.f, 0.f, 0.f);
    float4 a3 = make_float4(0.f, 0.f, 0.f, 0.f);
    int j = s;
    for (; j + 8 <= e; j += 8) {
        int s0 = g_csr_src[j],     s1 = g_csr_src[j + 1];
        int s2 = g_csr_src[j + 2], s3 = g_csr_src[j + 3];
        int s4 = g_csr_src[j + 4], s5 = g_csr_src[j + 5];
        int s6 = g_csr_src[j + 6], s7 = g_csr_src[j + 7];
        float4 v0 = *((const float4*)(in + (size_t)s0 * HDIM) + lane);
        float4 v1 = *((const float4*)(in + (size_t)s1 * HDIM) + lane);
        float4 v2 = *((const float4*)(in + (size_t)s2 * HDIM) + lane);
        float4 v3 = *((const float4*)(in + (size_t)s3 * HDIM) + lane);
        float4 v4 = *((const float4*)(in + (size_t)s4 * HDIM) + lane);
        float4 v5 = *((const float4*)(in + (size_t)s5 * HDIM) + lane);
        float4 v6 = *((const float4*)(in + (size_t)s6 * HDIM) + lane);
        float4 v7 = *((const float4*)(in + (size_t)s7 * HDIM) + lane);
        a0.x += v0.x; a0.y += v0.y; a0.z += v0.z; a0.w += v0.w;
        a1.x += v1.x; a1.y += v1.y; a1.z += v1.z; a1.w += v1.w;
        a2.x += v2.x; a2.y += v2.y; a2.z += v2.z; a2.w += v2.w;
        a3.x += v3.x; a3.y += v3.y; a3.z += v3.z; a3.w += v3.w;
        a0.x += v4.x; a0.y += v4.y; a0.z += v4.z; a0.w += v4.w;
        a1.x += v5.x; a1.y += v5.y; a1.z += v5.z; a1.w += v5.w;
        a2.x += v6.x; a2.y += v6.y; a2.z += v6.z; a2.w += v6.w;
        a3.x += v7.x; a3.y += v7.y; a3.z += v7.z; a3.w += v7.w;
    }
    for (; j + 2 <= e; j += 2) {
        int s0 = g_csr_src[j], s1 = g_csr_src[j + 1];
        float4 v0 = *((const float4*)(in + (size_t)s0 * HDIM) + lane);
        float4 v1 = *((const float4*)(in + (size_t)s1 * HDIM) + lane);
        a0.x += v0.x; a0.y += v0.y; a0.z += v0.z; a0.w += v0.w;
        a1.x += v1.x; a1.y += v1.y; a1.z += v1.z; a1.w += v1.w;
    }
    if (j < e) {
        int s0 = g_csr_src[j];
        float4 v0 = *((const float4*)(in + (size_t)s0 * HDIM) + lane);
        a0.x += v0.x; a0.y += v0.y; a0.z += v0.z; a0.w += v0.w;
    }
    float4 acc;
    acc.x = (a0.x + a1.x) + (a2.x + a3.x);
    acc.y = (a0.y + a1.y) + (a2.y + a3.y);
    acc.z = (a0.z + a1.z) + (a2.z + a3.z);
    acc.w = (a0.w + a1.w) + (a2.w + a3.w);
    float inv = 1.0f / (float)max(e - s, 1);
    acc.x *= inv; acc.y *= inv; acc.z *= inv; acc.w *= inv;
    __nv_bfloat16 h0, l0, h1, l1, h2, l2, h3, l3;
    split_bf16(acc.x, h0, l0); split_bf16(acc.y, h1, l1);
    split_bf16(acc.z, h2, l2); split_bf16(acc.w, h3, l3);
    uint2 hv = make_uint2(pack2(h0, h1), pack2(h2, h3));
    uint2 lv = make_uint2(pack2(l0, l1), pack2(l2, l3));
    *((uint2*)(g_aggh + (size_t)gw * HDIM) + lane) = hv;
    *((uint2*)(g_aggl + (size_t)gw * HDIM) + lane) = lv;
}

// ================= GEMM building blocks =================
#define APAD 40
#define HPAD 136
#define TILEB 10240
#define STAGEB (2 * TILEB)

__device__ __forceinline__ void issue_tile(uint32_t dh, uint32_t dl,
                                           const __nv_bfloat16* sh, const __nv_bfloat16* sl,
                                           size_t rstride, int rclamp, int coff, int t) {
#pragma unroll
    for (int it = 0; it < 2; it++) {
        int q = t + it * 256;
        int row = q >> 2, u = q & 3;
        int gr = min(row, rclamp);
        const __nv_bfloat16* ph = sh + (size_t)gr * rstride + coff + u * 8;
        const __nv_bfloat16* pl = sl + (size_t)gr * rstride + coff + u * 8;
        CP16(dh + row * 80 + u * 16, ph);
        CP16(dl + row * 80 + u * 16, pl);
    }
}

__device__ __forceinline__ void mma_step(const __nv_bfloat16* Ah, const __nv_bfloat16* Al, int lda,
                                         int akbase,
                                         const __nv_bfloat16* Bh, const __nv_bfloat16* Bl,
                                         int wm, int wn, int tgrp, int trow,
                                         float acc[2][8][4]) {
#pragma unroll
    for (int ks = 0; ks < 2; ks++) {
        int ak = akbase + ks * 16;
        int bk = ks * 16;
        uint32_t ahf[2][4], alf[2][4];
#pragma unroll
        for (int mf = 0; mf < 2; mf++) {
            int ar = wm * 32 + mf * 16 + (tgrp & 1) * 8 + trow;
            int ac = ak + (tgrp >> 1) * 8;
            LDSM_X4(ahf[mf][0], ahf[mf][1], ahf[mf][2], ahf[mf][3], smem_u32(&Ah[ar * lda + ac]));
            LDSM_X4(alf[mf][0], alf[mf][1], alf[mf][2], alf[mf][3], smem_u32(&Al[ar * lda + ac]));
        }
#pragma unroll
        for (int np = 0; np < 4; np++) {
            int br = wn * 64 + np * 16 + (tgrp >> 1) * 8 + trow;
            int bc = bk + (tgrp & 1) * 8;
            uint32_t bh0, bh1, bh2, bh3, bl0, bl1, bl2, bl3;
            LDSM_X4(bh0, bh1, bh2, bh3, smem_u32(&Bh[br * APAD + bc]));
            LDSM_X4(bl0, bl1, bl2, bl3, smem_u32(&Bl[br * APAD + bc]));
#pragma unroll
            for (int mf = 0; mf < 2; mf++) {
                MMA_BF16(acc[mf][np * 2],     ahf[mf], bh0, bh1);
                MMA_BF16(acc[mf][np * 2],     ahf[mf], bl0, bl1);
                MMA_BF16(acc[mf][np * 2],     alf[mf], bh0, bh1);
                MMA_BF16(acc[mf][np * 2 + 1], ahf[mf], bh2, bh3);
                MMA_BF16(acc[mf][np * 2 + 1], ahf[mf], bl2, bl3);
                MMA_BF16(acc[mf][np * 2 + 1], alf[mf], bh2, bh3);
            }
        }
    }
}

// ---------------- partial GEMM (side stream): out = A @ W[:,128..255]^T ----------------
// mode 0: A = Afp (fp32, convert in-kernel). mode 1: A = g_h1h/g_h1l (pre-split).
__global__ void __launch_bounds__(256)
xgemm_kernel(const float* __restrict__ Afp, int mode, int woff,
             float* __restrict__ outp, int M) {
    __shared__ __nv_bfloat16 Ah[128 * APAD], Al[128 * APAD];
    __shared__ __nv_bfloat16 Bh[128 * APAD], Bl[128 * APAD];
    int t = threadIdx.x, lane = t & 31, wid = t >> 5;
    int wm = wid >> 1, wn = wid & 1;
    int m0 = blockIdx.x * 128;
    int tgrp = lane >> 3, trow = lane & 7;

    float acc[2][8][4];
#pragma unroll
    for (int i = 0; i < 2; i++)
#pragma unroll
        for (int j = 0; j < 8; j++)
#pragma unroll
            for (int k = 0; k < 4; k++) acc[i][j][k] = 0.f;

    for (int ch = 0; ch < 4; ch++) {
        int row = t >> 1;
        int cb  = (t & 1) * 16;
        int gr  = min(m0 + row, M - 1);
        if (mode == 0) {
            const float4* src = (const float4*)(Afp + (size_t)gr * HDIM + ch * 32 + cb);
#pragma unroll
            for (int i = 0; i < 4; i++) {
                float4 f = src[i];
                __nv_bfloat16 h0, h1, h2, h3, l0, l1, l2, l3;
                split_bf16(f.x, h0, l0); split_bf16(f.y, h1, l1);
                split_bf16(f.z, h2, l2); split_bf16(f.w, h3, l3);
                *(uint2*)&Ah[row * APAD + cb + i * 4] = make_uint2(pack2(h0, h1), pack2(h2, h3));
                *(uint2*)&Al[row * APAD + cb + i * 4] = make_uint2(pack2(l0, l1), pack2(l2, l3));
            }
        } else {
            const uint4* ph = (const uint4*)(g_h1h + (size_t)gr * HDIM + ch * 32 + cb);
            const uint4* pl = (const uint4*)(g_h1l + (size_t)gr * HDIM + ch * 32 + cb);
            *(uint4*)&Ah[row * APAD + cb]     = ph[0];
            *(uint4*)&Ah[row * APAD + cb + 8] = ph[1];
            *(uint4*)&Al[row * APAD + cb]     = pl[0];
            *(uint4*)&Al[row * APAD + cb + 8] = pl[1];
        }
        // B: W rows, k columns 128 + ch*32
        const __nv_bfloat16* wh = g_Wh  + woff + (size_t)row * 256 + 128 + ch * 32 + cb;
        const __nv_bfloat16* wl = g_Wlo + woff + (size_t)row * 256 + 128 + ch * 32 + cb;
        *(uint4*)&Bh[row * APAD + cb]     = *(const uint4*)wh;
        *(uint4*)&Bh[row * APAD + cb + 8] = *(const uint4*)(wh + 8);
        *(uint4*)&Bl[row * APAD + cb]     = *(const uint4*)wl;
        *(uint4*)&Bl[row * APAD + cb + 8] = *(const uint4*)(wl + 8);
        __syncthreads();
        mma_step(Ah, Al, APAD, 0, Bh, Bl, wm, wn, tgrp, trow, acc);
        __syncthreads();
    }
    int qrow = lane >> 2, qcol = (lane & 3) * 2;
#pragma unroll
    for (int mf = 0; mf < 2; mf++)
#pragma unroll
        for (int nf = 0; nf < 8; nf++) {
            int n = wn * 64 + nf * 8 + qcol;
#pragma unroll
            for (int half = 0; half < 2; half++) {
                int gr = m0 + wm * 32 + mf * 16 + half * 8 + qrow;
                if (gr < M)
                    *(float2*)(outp + (size_t)gr * HDIM + n) =
                        make_float2(acc[mf][nf][half * 2], acc[mf][nf][half * 2 + 1]);
            }
        }
}

// ---------------- layer-1 main GEMM: h1 = relu(agg @ Wl1^T + xp1 + b1) ----------------
#define T1_SMEM (4 * STAGEB)
__global__ void __launch_bounds__(256)
tgemm_kernel(const float* __restrict__ bias, float* __restrict__ outp, int M) {
    extern __shared__ __nv_bfloat16 sm[];
    uint32_t sb = smem_u32(sm);
    int t = threadIdx.x, lane = t & 31, wid = t >> 5;
    int wm = wid >> 1, wn = wid & 1;
    int m0 = blockIdx.x * 128;
    int rclamp = M - 1 - m0;
    int tgrp = lane >> 3, trow = lane & 7;

    float acc[2][8][4];
#pragma unroll
    for (int i = 0; i < 2; i++)
#pragma unroll
        for (int j = 0; j < 8; j++)
#pragma unroll
            for (int k = 0; k < 4; k++) acc[i][j][k] = 0.f;

    const __nv_bfloat16* aggh = g_aggh + (size_t)m0 * HDIM;
    const __nv_bfloat16* aggl = g_aggl + (size_t)m0 * HDIM;

    issue_tile(sb + 2 * STAGEB, sb + 2 * STAGEB + TILEB, aggh, aggl, HDIM, rclamp, 0, t);
    issue_tile(sb, sb + TILEB, g_Wh, g_Wlo, 256, 127, 0, t);
    CP_COMMIT();
    for (int ch = 0; ch < 4; ch++) {
        int cur = ch & 1, nxt = (ch + 1) & 1;
        if (ch + 1 < 4) {
            int nc = ch + 1;
            issue_tile(sb + 2 * STAGEB + nxt * STAGEB, sb + 2 * STAGEB + nxt * STAGEB + TILEB,
                       aggh, aggl, HDIM, rclamp, nc * 32, t);
            issue_tile(sb + nxt * STAGEB, sb + nxt * STAGEB + TILEB, g_Wh, g_Wlo, 256, 127, nc * 32, t);
        }
        CP_COMMIT();
        CP_WAIT1();
        __syncthreads();
        mma_step(sm + (2 * STAGEB + cur * STAGEB) / 2, sm + (2 * STAGEB + cur * STAGEB + TILEB) / 2,
                 APAD, 0,
                 sm + (cur * STAGEB) / 2, sm + (cur * STAGEB + TILEB) / 2,
                 wm, wn, tgrp, trow, acc);
        __syncthreads();
    }
    // epilogue: + xp1 + bias, relu -> h1 fp32 AND pre-split bf16
    int qrow = lane >> 2, qcol = (lane & 3) * 2;
#pragma unroll
    for (int mf = 0; mf < 2; mf++)
#pragma unroll
        for (int nf = 0; nf < 8; nf++) {
            int n = wn * 64 + nf * 8 + qcol;
            float bx = __ldg(bias + n), by = __ldg(bias + n + 1);
#pragma unroll
            for (int half = 0; half < 2; half++) {
                int gr = m0 + wm * 32 + mf * 16 + half * 8 + qrow;
                if (gr < M) {
                    float2 xp = *(const float2*)(g_xp1 + (size_t)gr * HDIM + n);
                    float v0 = fmaxf(acc[mf][nf][half * 2]     + xp.x + bx, 0.f);
                    float v1 = fmaxf(acc[mf][nf][half * 2 + 1] + xp.y + by, 0.f);
                    *(float2*)(outp + (size_t)gr * HDIM + n) = make_float2(v0, v1);
                    __nv_bfloat16 h0, l0, h1b, l1b;
                    split_bf16(v0, h0, l0);
                    split_bf16(v1, h1b, l1b);
                    *(uint32_t*)(g_h1h + (size_t)gr * HDIM + n) = pack2(h0, h1b);
                    *(uint32_t*)(g_h1l + (size_t)gr * HDIM + n) = pack2(l0, l1b);
                }
            }
        }
}

// ---------------- fused layer-2 + U: h2 = relu(agg@Wl2^T + xp2 + b2) stays in smem ----------------
#define L2U_SMEM (2 * STAGEB + 2 * 128 * HPAD * 2)   // 110592 B
__global__ void __launch_bounds__(256)
layer2u_kernel(const float* __restrict__ b2, int M) {
    extern __shared__ __nv_bfloat16 sm[];
    uint32_t sb = smem_u32(sm);
    const uint32_t XOFF = 2 * STAGEB;
    __nv_bfloat16* H2h = sm + XOFF / 2;
    __nv_bfloat16* H2l = H2h + 128 * HPAD;

    int t = threadIdx.x, lane = t & 31, wid = t >> 5;
    int wm = wid >> 1, wn = wid & 1;
    int m0 = blockIdx.x * 128;
    int rclamp = M - 1 - m0;
    int tgrp = lane >> 3, trow = lane & 7;
    int qrow = lane >> 2, qcol = (lane & 3) * 2;

    float acc[2][8][4];
#pragma unroll
    for (int i = 0; i < 2; i++)
#pragma unroll
        for (int j = 0; j < 8; j++)
#pragma unroll
            for (int k = 0; k < 4; k++) acc[i][j][k] = 0.f;

    const __nv_bfloat16* a0h = g_aggh + (size_t)m0 * HDIM;
    const __nv_bfloat16* a0l = g_aggl + (size_t)m0 * HDIM;

    // ---- phase A: agg @ Wl2^T (4 chunks) ----
    issue_tile(sb + XOFF, sb + XOFF + TILEB, a0h, a0l, HDIM, rclamp, 0, t);
    issue_tile(sb, sb + TILEB, g_Wh + 32768, g_Wlo + 32768, 256, 127, 0, t);
    CP_COMMIT();
    for (int ch = 0; ch < 4; ch++) {
        int cur = ch & 1, nxt = (ch + 1) & 1;
        if (ch + 1 < 4) {
            int nc = ch + 1;
            issue_tile(sb + XOFF + nxt * STAGEB, sb + XOFF + nxt * STAGEB + TILEB,
                       a0h, a0l, HDIM, rclamp, nc * 32, t);
            issue_tile(sb + nxt * STAGEB, sb + nxt * STAGEB + TILEB,
                       g_Wh + 32768, g_Wlo + 32768, 256, 127, nc * 32, t);
        }
        CP_COMMIT();
        CP_WAIT1();
        __syncthreads();
        mma_step(sm + (XOFF + cur * STAGEB) / 2, sm + (XOFF + cur * STAGEB + TILEB) / 2,
                 APAD, 0,
                 sm + (cur * STAGEB) / 2, sm + (cur * STAGEB + TILEB) / 2,
                 wm, wn, tgrp, trow, acc);
        __syncthreads();
    }
    // h2 = relu(acc + xp2 + b2) -> smem bf16 hi/lo
#pragma unroll
    for (int mf = 0; mf < 2; mf++)
#pragma unroll
        for (int nf = 0; nf < 8; nf++) {
            int n = wn * 64 + nf * 8 + qcol;
            float bx = __ldg(b2 + n), by = __ldg(b2 + n + 1);
#pragma unroll
            for (int half = 0; half < 2; half++) {
                int row = wm * 32 + mf * 16 + half * 8 + qrow;
                int gx = min(m0 + row, M - 1);
                float2 xp = *(const float2*)(g_xp2 + (size_t)gx * HDIM + n);
                float v0 = fmaxf(acc[mf][nf][half * 2]     + xp.x + bx, 0.f);
                float v1 = fmaxf(acc[mf][nf][half * 2 + 1] + xp.y + by, 0.f);
                __nv_bfloat16 h0, l0, h1b, l1b;
                split_bf16(v0, h0, l0);
                split_bf16(v1, h1b, l1b);
                H2h[row * HPAD + n]     = h0;
                H2h[row * HPAD + n + 1] = h1b;
                H2l[row * HPAD + n]     = l0;
                H2l[row * HPAD + n + 1] = l1b;
            }
        }
    __syncthreads();

    // ---- phase B: U[:, y*128..] = h2 @ W3y^T, 8 B-rounds (y = r>>2) ----
    issue_tile(sb, sb + TILEB, g_Wh + 65536, g_Wlo + 65536, 128, 127, 0, t);
    CP_COMMIT();
    for (int r = 0; r < 8; r++) {
        int cur = r & 1, nxt = (r + 1) & 1;
        if ((r & 3) == 0) {
#pragma unroll
            for (int i = 0; i < 2; i++)
#pragma unroll
                for (int j = 0; j < 8; j++)
#pragma unroll
                    for (int k = 0; k < 4; k++) acc[i][j][k] = 0.f;
        }
        if (r + 1 < 8) {
            int nr = r + 1;
            issue_tile(sb + nxt * STAGEB, sb + nxt * STAGEB + TILEB,
                       g_Wh + 65536 + (nr >> 2) * 16384, g_Wlo + 65536 + (nr >> 2) * 16384,
                       128, 127, (nr & 3) * 32, t);
        }
        CP_COMMIT();
        CP_WAIT1();
        __syncthreads();
        mma_step(H2h, H2l, HPAD, (r & 3) * 32,
                 sm + (cur * STAGEB) / 2, sm + (cur * STAGEB + TILEB) / 2,
                 wm, wn, tgrp, trow, acc);
        __syncthreads();
        if ((r & 3) == 3) {
            int y = r >> 2;
#pragma unroll
            for (int mf = 0; mf < 2; mf++)
#pragma unroll
                for (int nf = 0; nf < 8; nf++) {
                    int n = wn * 64 + nf * 8 + qcol;
#pragma unroll
                    for (int half = 0; half < 2; half++) {
                        int gr = m0 + wm * 32 + mf * 16 + half * 8 + qrow;
                        if (gr < M) {
                            *(float2*)(g_U + (size_t)gr * 256 + y * 128 + n) =
                                make_float2(acc[mf][nf][half * 2], acc[mf][nf][half * 2 + 1]);
                        }
                    }
                }
        }
    }
}

// ---------------- pair head: sigmoid(W4 . relu(Ua[a]+Ub[b]+b3) + b4) ----------------
__global__ void __launch_bounds__(256)
pair_kernel(const int* __restrict__ pairs,
            const float* __restrict__ b3, const float* __restrict__ W4,
            const float* __restrict__ b4, float* __restrict__ out, int P) {
    int w    = (blockIdx.x * blockDim.x + threadIdx.x) >> 5;
    int lane = threadIdx.x & 31;
    if (w >= P) return;
    int na = __ldg(&pairs[2 * w]);
    int nb = __ldg(&pairs[2 * w + 1]);
    float4 ua = *((const float4*)(g_U + (size_t)na * 256) + lane);
    float4 ub = *((const float4*)(g_U + (size_t)nb * 256 + 128) + lane);
    float4 bv = *((const float4*)b3 + lane);
    float4 wv = *((const float4*)W4 + lane);
    float s = fmaxf(ua.x + ub.x + bv.x, 0.f) * wv.x
            + fmaxf(ua.y + ub.y + bv.y, 0.f) * wv.y
            + fmaxf(ua.z + ub.z + bv.z, 0.f) * wv.z
            + fmaxf(ua.w + ub.w + bv.w, 0.f) * wv.w;
#pragma unroll
    for (int o = 16; o > 0; o >>= 1)
        s += __shfl_xor_sync(0xffffffffu, s, o);
    if (lane == 0) out[w] = 1.0f / (1.0f + __expf(-(s + b4[0])));
}

// ---------------- launch ----------------
extern "C" void kernel_launch(void* const* d_in, const int* in_sizes, int n_in,
                              void* d_out, int out_size) {
    const float* x    = (const float*)d_in[0];
    const int*   edge = (const int*)d_in[1];
    const int*   prs  = (const int*)d_in[2];
    const float* Wl1  = (const float*)d_in[3];
    const float* Wr1  = (const float*)d_in[4];
    const float* b1   = (const float*)d_in[5];
    const float* Wl2  = (const float*)d_in[6];
    const float* Wr2  = (const float*)d_in[7];
    const float* b2   = (const float*)d_in[8];
    const float* W3   = (const float*)d_in[9];
    const float* b3   = (const float*)d_in[10];
    const float* W4   = (const float*)d_in[11];
    const float* b4   = (const float*)d_in[12];
    float* out = (float*)d_out;

    const int E = in_sizes[1] / 2;
    const int P = in_sizes[2] / 2;
    const int M = N_NODES;
    const int* src = edge;
    const int* dst = edge + E;

    float* g_h1_p;  cudaGetSymbolAddress((void**)&g_h1_p, g_h1);
    float* g_xp1_p; cudaGetSymbolAddress((void**)&g_xp1_p, g_xp1);
    float* g_xp2_p; cudaGetSymbolAddress((void**)&g_xp2_p, g_xp2);

    static cudaStream_t s2 = 0;
    static cudaEvent_t evW = 0, ev2 = 0, evH = 0, ev3 = 0;
    if (!s2) {
        cudaStreamCreateWithFlags(&s2, cudaStreamNonBlocking);
        cudaEventCreateWithFlags(&evW, cudaEventDisableTiming);
        cudaEventCreateWithFlags(&ev2, cudaEventDisableTiming);
        cudaEventCreateWithFlags(&evH, cudaEventDisableTiming);
        cudaEventCreateWithFlags(&ev3, cudaEventDisableTiming);
        cudaFuncSetAttribute(tgemm_kernel,   cudaFuncAttributeMaxDynamicSharedMemorySize, T1_SMEM);
        cudaFuncSetAttribute(layer2u_kernel, cudaFuncAttributeMaxDynamicSharedMemorySize, L2U_SMEM);
    }

    const int aggBlocks = (N_NODES * 32 + 255) / 256;
    const int mTiles = (M + 127) / 128;   // 391

    // CSR build + weight split (g_deg is zeroed: BSS init / previous scan_deg run)
    countsplit_kernel<<<(E + 255) / 256, 256>>>(dst, E, Wl1, Wr1, Wl2, Wr2, W3);

    // side stream: xp1 = x @ Wr1^T (depends only on weights)
    cudaEventRecord(evW, 0);
    cudaStreamWaitEvent(s2, evW, 0);
    xgemm_kernel<<<mTiles, 256, 0, s2>>>(x, 0, 0, g_xp1_p, M);
    cudaEventRecord(ev2, s2);

    scan_deg_kernel<<<1, 1024>>>(E);
    fill_csr_kernel<<<(E + 255) / 256, 256>>>(src, dst, E);
    agg_mean_kernel<<<aggBlocks, 256>>>(x, 0);

    cudaStreamWaitEvent(0, ev2, 0);
    tgemm_kernel<<<mTiles, 256, T1_SMEM>>>(b1, g_h1_p, M);

    // side stream: xp2 = h1 @ Wr2^T (overlaps agg2)
    cudaEventRecord(evH, 0);
    cudaStreamWaitEvent(s2, evH, 0);
    xgemm_kernel<<<mTiles, 256, 0, s2>>>((const float*)0, 1, 32768, g_xp2_p, M);
    cudaEventRecord(ev3, s2);

    agg_mean_kernel<<<aggBlocks, 256>>>(x, 1);

    cudaStreamWaitEvent(0, ev3, 0);
    layer2u_kernel<<<mTiles, 256, L2U_SMEM>>>(b2, M);
    pair_kernel<<<(P * 32 + 255) / 256, 256>>>(prs, b3, W4, b4, out, P);
}

// round 14
// speedup vs baseline: 1.0814x; 1.0814x over previous
#include <cuda_runtime.h>
#include <cuda_bf16.h>
#include <math.h>
#include <stdint.h>

#define N_NODES 50000
#define E_EDGES 500000
#define HDIM    128

// ---- scratch (device globals; no allocation in kernel_launch) ----
__device__ int   g_deg[N_NODES];          // zeroed at BSS init; re-zeroed by scan_deg each run
__device__ int   g_rowstart[N_NODES + 1];
__device__ int   g_cursor[N_NODES];
__device__ int   g_csr_src[E_EDGES];
__device__ float g_h1  [(size_t)N_NODES * HDIM];
__device__ float g_U   [(size_t)N_NODES * 256];
// pre-split operands (bf16 hi/lo)
__device__ __nv_bfloat16 g_aggh[(size_t)N_NODES * HDIM];
__device__ __nv_bfloat16 g_aggl[(size_t)N_NODES * HDIM];
__device__ __nv_bfloat16 g_h1h [(size_t)N_NODES * HDIM];
__device__ __nv_bfloat16 g_h1l [(size_t)N_NODES * HDIM];
// split weights bf16 hi/lo, [n][k] row-major:
// L1 [128][256] @0, L2 [128][256] @32768, W3a [128][128] @65536, W3b [128][128] @81920
__device__ __nv_bfloat16 g_Wh[98304];
__device__ __nv_bfloat16 g_Wlo[98304];

__device__ __forceinline__ uint32_t smem_u32(const void* p) {
    uint32_t a;
    asm("{ .reg .u64 t; cvta.to.shared.u64 t, %1; cvt.u32.u64 %0, t; }" : "=r"(a) : "l"(p));
    return a;
}
#define LDSM_X4(r0, r1, r2, r3, a) \
    asm volatile("ldmatrix.sync.aligned.m8n8.x4.shared.b16 {%0,%1,%2,%3}, [%4];" \
        : "=r"(r0), "=r"(r1), "=r"(r2), "=r"(r3) : "r"(a))
#define MMA_BF16(c, a, b0, b1) \
    asm volatile("mma.sync.aligned.m16n8k16.row.col.f32.bf16.bf16.f32 " \
        "{%0,%1,%2,%3}, {%4,%5,%6,%7}, {%8,%9}, {%0,%1,%2,%3};" \
        : "+f"((c)[0]), "+f"((c)[1]), "+f"((c)[2]), "+f"((c)[3]) \
        : "r"((a)[0]), "r"((a)[1]), "r"((a)[2]), "r"((a)[3]), "r"(b0), "r"(b1))
#define CP16(dst, src) \
    asm volatile("cp.async.ca.shared.global [%0], [%1], 16;" :: "r"(dst), "l"(src))
#define CP_COMMIT() asm volatile("cp.async.commit_group;" ::: "memory")
#define CP_WAIT1()  asm volatile("cp.async.wait_group 1;" ::: "memory")

__device__ __forceinline__ void split_bf16(float v, __nv_bfloat16& h, __nv_bfloat16& l) {
    h = __float2bfloat16(v);
    l = __float2bfloat16(v - __bfloat162float(h));
}
__device__ __forceinline__ uint32_t pack2(__nv_bfloat16 a, __nv_bfloat16 b) {
    return (uint32_t)__bfloat16_as_ushort(a) | ((uint32_t)__bfloat16_as_ushort(b) << 16);
}

// ---------------- fused: degree count + weight split ----------------
__global__ void countsplit_kernel(const int* __restrict__ dst, int E,
                                  const float* __restrict__ Wl1, const float* __restrict__ Wr1,
                                  const float* __restrict__ Wl2, const float* __restrict__ Wr2,
                                  const float* __restrict__ W3) {
    int i = blockIdx.x * blockDim.x + threadIdx.x;
    if (i < E) atomicAdd(&g_deg[dst[i]], 1);
    if (i < 98304) {
        float v;
        if (i < 32768) {
            int n = i >> 8, k = i & 255;
            v = (k < 128) ? Wl1[n * 128 + k] : Wr1[n * 128 + (k - 128)];
        } else if (i < 65536) {
            int j = i - 32768;
            int n = j >> 8, k = j & 255;
            v = (k < 128) ? Wl2[n * 128 + k] : Wr2[n * 128 + (k - 128)];
        } else {
            int j = i - 65536;
            int half = j >> 14;
            int jj = j & 16383;
            int n = jj >> 7, k = jj & 127;
            v = W3[n * 256 + half * 128 + k];
        }
        __nv_bfloat16 h, l;
        split_bf16(v, h, l);
        g_Wh[i]  = h;
        g_Wlo[i] = l;
    }
}

// scan + re-zero g_deg (keeps the zeroed invariant for the next graph replay)
__global__ void scan_deg_kernel(int E) {
    __shared__ int ssum[1024];
    int tid = threadIdx.x;
    const int chunk = (N_NODES + 1023) / 1024;
    int start = tid * chunk;
    int end = min(start + chunk, N_NODES);
    int s = 0;
    for (int i = start; i < end; i++) s += g_deg[i];
    ssum[tid] = s;
    __syncthreads();
    for (int d = 1; d < 1024; d <<= 1) {
        int v = (tid >= d) ? ssum[tid - d] : 0;
        __syncthreads();
        ssum[tid] += v;
        __syncthreads();
    }
    int run = ssum[tid] - s;
    for (int i = start; i < end; i++) {
        g_rowstart[i] = run;
        g_cursor[i]   = run;
        run += g_deg[i];
    }
    if (tid == 1023) g_rowstart[N_NODES] = E;
    for (int i = start; i < end; i++) g_deg[i] = 0;
}

__global__ void fill_csr_kernel(const int* __restrict__ src,
                                const int* __restrict__ dst, int E) {
    int i = blockIdx.x * blockDim.x + threadIdx.x;
    if (i < E) {
        int p = atomicAdd(&g_cursor[dst[i]], 1);
        g_csr_src[p] = src[i];
    }
}

// ---------------- mean aggregation: warp per node, MLP=8; writes split bf16 ----------------
__global__ void agg_mean_kernel(const float* __restrict__ xin, int use_h1) {
    int gw   = (blockIdx.x * blockDim.x + threadIdx.x) >> 5;
    int lane = threadIdx.x & 31;
    if (gw >= N_NODES) return;
    const float* in = use_h1 ? g_h1 : xin;
    int s = g_rowstart[gw];
    int e = g_rowstart[gw + 1];
    float4 a0 = make_float4(0.f, 0.f, 0.f, 0.f);
    float4 a1 = make_float4(0.f, 0.f, 0.f, 0.f);
    float4 a2 = make_float4(0.f, 0.f, 0.f, 0.f);
    float4 a3 = make_float4(0.f, 0.f, 0.f, 0.f);
    int j = s;
    for (; j + 8 <= e; j += 8) {
        int s0 = g_csr_src[j],     s1 = g_csr_src[j + 1];
        int s2 = g_csr_src[j + 2], s3 = g_csr_src[j + 3];
        int s4 = g_csr_src[j + 4], s5 = g_csr_src[j + 5];
        int s6 = g_csr_src[j + 6], s7 = g_csr_src[j + 7];
        float4 v0 = *((const float4*)(in + (size_t)s0 * HDIM) + lane);
        float4 v1 = *((const float4*)(in + (size_t)s1 * HDIM) + lane);
        float4 v2 = *((const float4*)(in + (size_t)s2 * HDIM) + lane);
        float4 v3 = *((const float4*)(in + (size_t)s3 * HDIM) + lane);
        float4 v4 = *((const float4*)(in + (size_t)s4 * HDIM) + lane);
        float4 v5 = *((const float4*)(in + (size_t)s5 * HDIM) + lane);
        float4 v6 = *((const float4*)(in + (size_t)s6 * HDIM) + lane);
        float4 v7 = *((const float4*)(in + (size_t)s7 * HDIM) + lane);
        a0.x += v0.x; a0.y += v0.y; a0.z += v0.z; a0.w += v0.w;
        a1.x += v1.x; a1.y += v1.y; a1.z += v1.z; a1.w += v1.w;
        a2.x += v2.x; a2.y += v2.y; a2.z += v2.z; a2.w += v2.w;
        a3.x += v3.x; a3.y += v3.y; a3.z += v3.z; a3.w += v3.w;
        a0.x += v4.x; a0.y += v4.y; a0.z += v4.z; a0.w += v4.w;
        a1.x += v5.x; a1.y += v5.y; a1.z += v5.z; a1.w += v5.w;
        a2.x += v6.x; a2.y += v6.y; a2.z += v6.z; a2.w += v6.w;
        a3.x += v7.x; a3.y += v7.y; a3.z += v7.z; a3.w += v7.w;
    }
    for (; j + 2 <= e; j += 2) {
        int s0 = g_csr_src[j], s1 = g_csr_src[j + 1];
        float4 v0 = *((const float4*)(in + (size_t)s0 * HDIM) + lane);
        float4 v1 = *((const float4*)(in + (size_t)s1 * HDIM) + lane);
        a0.x += v0.x; a0.y += v0.y; a0.z += v0.z; a0.w += v0.w;
        a1.x += v1.x; a1.y += v1.y; a1.z += v1.z; a1.w += v1.w;
    }
    if (j < e) {
        int s0 = g_csr_src[j];
        float4 v0 = *((const float4*)(in + (size_t)s0 * HDIM) + lane);
        a0.x += v0.x; a0.y += v0.y; a0.z += v0.z; a0.w += v0.w;
    }
    float4 acc;
    acc.x = (a0.x + a1.x) + (a2.x + a3.x);
    acc.y = (a0.y + a1.y) + (a2.y + a3.y);
    acc.z = (a0.z + a1.z) + (a2.z + a3.z);
    acc.w = (a0.w + a1.w) + (a2.w + a3.w);
    float inv = 1.0f / (float)max(e - s, 1);
    acc.x *= inv; acc.y *= inv; acc.z *= inv; acc.w *= inv;
    __nv_bfloat16 h0, l0, h1, l1, h2, l2, h3, l3;
    split_bf16(acc.x, h0, l0); split_bf16(acc.y, h1, l1);
    split_bf16(acc.z, h2, l2); split_bf16(acc.w, h3, l3);
    uint2 hv = make_uint2(pack2(h0, h1), pack2(h2, h3));
    uint2 lv = make_uint2(pack2(l0, l1), pack2(l2, l3));
    *((uint2*)(g_aggh + (size_t)gw * HDIM) + lane) = hv;
    *((uint2*)(g_aggl + (size_t)gw * HDIM) + lane) = lv;
}

// ================= GEMM building blocks =================
// Block: 256 thr (8 warps, 4m x 2n), tile 128x128, BK=32. Warp tile 32x64.
#define APAD 40    // 80B smem row stride, conflict-free ldmatrix, 16B aligned rows
#define HPAD 136   // 272B row stride for h2 smem tile
#define TILEB 10240                       // one 128xAPAD bf16 tile
#define STAGEB (2 * TILEB)                // Ah+Al or Bh+Bl per stage

// cp.async issue of one 128x32 bf16 tile pair (hi/lo), 2x16B per thread each
__device__ __forceinline__ void issue_tile(uint32_t dh, uint32_t dl,
                                           const __nv_bfloat16* sh, const __nv_bfloat16* sl,
                                           size_t rstride, int rclamp, int coff, int t) {
#pragma unroll
    for (int it = 0; it < 2; it++) {
        int q = t + it * 256;
        int row = q >> 2, u = q & 3;
        int gr = min(row, rclamp);
        const __nv_bfloat16* ph = sh + (size_t)gr * rstride + coff + u * 8;
        const __nv_bfloat16* pl = sl + (size_t)gr * rstride + coff + u * 8;
        CP16(dh + row * 80 + u * 16, ph);
        CP16(dl + row * 80 + u * 16, pl);
    }
}

// one BK=32 compute step; A at row-stride lda (elements), B at APAD
__device__ __forceinline__ void mma_step(const __nv_bfloat16* Ah, const __nv_bfloat16* Al, int lda,
                                         int akbase,
                                         const __nv_bfloat16* Bh, const __nv_bfloat16* Bl,
                                         int wm, int wn, int tgrp, int trow,
                                         float acc[2][8][4]) {
#pragma unroll
    for (int ks = 0; ks < 2; ks++) {
        int ak = akbase + ks * 16;
        int bk = ks * 16;
        uint32_t ahf[2][4], alf[2][4];
#pragma unroll
        for (int mf = 0; mf < 2; mf++) {
            int ar = wm * 32 + mf * 16 + (tgrp & 1) * 8 + trow;
            int ac = ak + (tgrp >> 1) * 8;
            LDSM_X4(ahf[mf][0], ahf[mf][1], ahf[mf][2], ahf[mf][3], smem_u32(&Ah[ar * lda + ac]));
            LDSM_X4(alf[mf][0], alf[mf][1], alf[mf][2], alf[mf][3], smem_u32(&Al[ar * lda + ac]));
        }
#pragma unroll
        for (int np = 0; np < 4; np++) {
            int br = wn * 64 + np * 16 + (tgrp >> 1) * 8 + trow;
            int bc = bk + (tgrp & 1) * 8;
            uint32_t bh0, bh1, bh2, bh3, bl0, bl1, bl2, bl3;
            LDSM_X4(bh0, bh1, bh2, bh3, smem_u32(&Bh[br * APAD + bc]));
            LDSM_X4(bl0, bl1, bl2, bl3, smem_u32(&Bl[br * APAD + bc]));
#pragma unroll
            for (int mf = 0; mf < 2; mf++) {
                MMA_BF16(acc[mf][np * 2],     ahf[mf], bh0, bh1);
                MMA_BF16(acc[mf][np * 2],     ahf[mf], bl0, bl1);
                MMA_BF16(acc[mf][np * 2],     alf[mf], bh0, bh1);
                MMA_BF16(acc[mf][np * 2 + 1], ahf[mf], bh2, bh3);
                MMA_BF16(acc[mf][np * 2 + 1], ahf[mf], bl2, bl3);
                MMA_BF16(acc[mf][np * 2 + 1], alf[mf], bh2, bh3);
            }
        }
    }
}

// ---------------- layer-1 GEMM: h1 = relu([agg|x] @ [Wl1|Wr1]^T + b1) ----------------
// dyn smem: B stages [0,2*STAGEB) | A stages [2*STAGEB, 4*STAGEB)  = 81920 B
#define T1_SMEM (4 * STAGEB)
__global__ void __launch_bounds__(256)
tgemm_kernel(const float* __restrict__ x, const float* __restrict__ bias,
             float* __restrict__ outp, int M) {
    extern __shared__ __nv_bfloat16 sm[];
    uint32_t sb = smem_u32(sm);
    int t = threadIdx.x, lane = t & 31, wid = t >> 5;
    int wm = wid >> 1, wn = wid & 1;
    int m0 = blockIdx.x * 128;
    int rclamp = M - 1 - m0;
    int tgrp = lane >> 3, trow = lane & 7;

    float acc[2][8][4];
#pragma unroll
    for (int i = 0; i < 2; i++)
#pragma unroll
        for (int j = 0; j < 8; j++)
#pragma unroll
            for (int k = 0; k < 4; k++) acc[i][j][k] = 0.f;

    const __nv_bfloat16* aggh = g_aggh + (size_t)m0 * HDIM;
    const __nv_bfloat16* aggl = g_aggl + (size_t)m0 * HDIM;

    issue_tile(sb + 2 * STAGEB, sb + 2 * STAGEB + TILEB, aggh, aggl, HDIM, rclamp, 0, t);
    issue_tile(sb, sb + TILEB, g_Wh, g_Wlo, 256, 127, 0, t);
    CP_COMMIT();

    for (int ch = 0; ch < 8; ch++) {
        int cur = ch & 1, nxt = (ch + 1) & 1;
        float4 xr[4];
        bool havex = false;
        if (ch + 1 < 8) {
            int nc = ch + 1;
            int acol = (nc & 3) * 32;
            if (nc < 4) {
                issue_tile(sb + 2 * STAGEB + nxt * STAGEB, sb + 2 * STAGEB + nxt * STAGEB + TILEB,
                           aggh, aggl, HDIM, rclamp, acol, t);
            } else {
#pragma unroll
                for (int it = 0; it < 2; it++) {
                    int q = t + it * 256;
                    int row = q >> 2, u = q & 3;
                    int gr = min(m0 + row, M - 1);
                    const float4* p = (const float4*)(x + (size_t)gr * HDIM + acol + u * 8);
                    xr[it * 2]     = p[0];
                    xr[it * 2 + 1] = p[1];
                }
                havex = true;
            }
            issue_tile(sb + nxt * STAGEB, sb + nxt * STAGEB + TILEB, g_Wh, g_Wlo, 256, 127, nc * 32, t);
        }
        CP_COMMIT();
        CP_WAIT1();
        __syncthreads();
        mma_step(sm + (2 * STAGEB + cur * STAGEB) / 2, sm + (2 * STAGEB + cur * STAGEB + TILEB) / 2,
                 APAD, 0,
                 sm + (cur * STAGEB) / 2, sm + (cur * STAGEB + TILEB) / 2,
                 wm, wn, tgrp, trow, acc);
        __syncthreads();
        if (havex) {
            __nv_bfloat16* Ahn = sm + (2 * STAGEB + nxt * STAGEB) / 2;
            __nv_bfloat16* Aln = Ahn + TILEB / 2;
#pragma unroll
            for (int it = 0; it < 2; it++) {
                int q = t + it * 256;
                int row = q >> 2, u = q & 3;
                const float* f = (const float*)&xr[it * 2];
                __nv_bfloat16 hh[8], ll[8];
#pragma unroll
                for (int i = 0; i < 8; i++) split_bf16(f[i], hh[i], ll[i]);
                uint4 hv = make_uint4(pack2(hh[0], hh[1]), pack2(hh[2], hh[3]),
                                      pack2(hh[4], hh[5]), pack2(hh[6], hh[7]));
                uint4 lv = make_uint4(pack2(ll[0], ll[1]), pack2(ll[2], ll[3]),
                                      pack2(ll[4], ll[5]), pack2(ll[6], ll[7]));
                *(uint4*)&Ahn[row * APAD + u * 8] = hv;
                *(uint4*)&Aln[row * APAD + u * 8] = lv;
            }
        }
    }
    // epilogue: bias+relu -> h1 fp32 AND pre-split bf16
    int qrow = lane >> 2, qcol = (lane & 3) * 2;
#pragma unroll
    for (int mf = 0; mf < 2; mf++)
#pragma unroll
        for (int nf = 0; nf < 8; nf++) {
            int n = wn * 64 + nf * 8 + qcol;
            float bx = __ldg(bias + n), by = __ldg(bias + n + 1);
#pragma unroll
            for (int half = 0; half < 2; half++) {
                int gr = m0 + wm * 32 + mf * 16 + half * 8 + qrow;
                if (gr < M) {
                    float v0 = fmaxf(acc[mf][nf][half * 2]     + bx, 0.f);
                    float v1 = fmaxf(acc[mf][nf][half * 2 + 1] + by, 0.f);
                    *(float2*)(outp + (size_t)gr * HDIM + n) = make_float2(v0, v1);
                    __nv_bfloat16 h0, l0, h1b, l1b;
                    split_bf16(v0, h0, l0);
                    split_bf16(v1, h1b, l1b);
                    *(uint32_t*)(g_h1h + (size_t)gr * HDIM + n) = pack2(h0, h1b);
                    *(uint32_t*)(g_h1l + (size_t)gr * HDIM + n) = pack2(l0, l1b);
                }
            }
        }
}

// ---------------- fused layer-2 + U: h2 stays in smem ----------------
#define L2U_SMEM (2 * STAGEB + 2 * 128 * HPAD * 2)   // 110592 B
__global__ void __launch_bounds__(256)
layer2u_kernel(const float* __restrict__ b2, int M) {
    extern __shared__ __nv_bfloat16 sm[];
    uint32_t sb = smem_u32(sm);
    const uint32_t XOFF = 2 * STAGEB;
    __nv_bfloat16* H2h = sm + XOFF / 2;
    __nv_bfloat16* H2l = H2h + 128 * HPAD;

    int t = threadIdx.x, lane = t & 31, wid = t >> 5;
    int wm = wid >> 1, wn = wid & 1;
    int m0 = blockIdx.x * 128;
    int rclamp = M - 1 - m0;
    int tgrp = lane >> 3, trow = lane & 7;
    int qrow = lane >> 2, qcol = (lane & 3) * 2;

    float acc[2][8][4];
#pragma unroll
    for (int i = 0; i < 2; i++)
#pragma unroll
        for (int j = 0; j < 8; j++)
#pragma unroll
            for (int k = 0; k < 4; k++) acc[i][j][k] = 0.f;

    const __nv_bfloat16* a0h = g_aggh + (size_t)m0 * HDIM;
    const __nv_bfloat16* a0l = g_aggl + (size_t)m0 * HDIM;
    const __nv_bfloat16* a1h = g_h1h + (size_t)m0 * HDIM;
    const __nv_bfloat16* a1l = g_h1l + (size_t)m0 * HDIM;

    // ---- phase A: h2 = relu([agg|h1] @ [Wl2|Wr2]^T + b2) ----
    issue_tile(sb + XOFF, sb + XOFF + TILEB, a0h, a0l, HDIM, rclamp, 0, t);
    issue_tile(sb, sb + TILEB, g_Wh + 32768, g_Wlo + 32768, 256, 127, 0, t);
    CP_COMMIT();
    for (int ch = 0; ch < 8; ch++) {
        int cur = ch & 1, nxt = (ch + 1) & 1;
        if (ch + 1 < 8) {
            int nc = ch + 1;
            const __nv_bfloat16* sh = (nc < 4) ? a0h : a1h;
            const __nv_bfloat16* sl = (nc < 4) ? a0l : a1l;
            issue_tile(sb + XOFF + nxt * STAGEB, sb + XOFF + nxt * STAGEB + TILEB,
                       sh, sl, HDIM, rclamp, (nc & 3) * 32, t);
            issue_tile(sb + nxt * STAGEB, sb + nxt * STAGEB + TILEB,
                       g_Wh + 32768, g_Wlo + 32768, 256, 127, nc * 32, t);
        }
        CP_COMMIT();
        CP_WAIT1();
        __syncthreads();
        mma_step(sm + (XOFF + cur * STAGEB) / 2, sm + (XOFF + cur * STAGEB + TILEB) / 2,
                 APAD, 0,
                 sm + (cur * STAGEB) / 2, sm + (cur * STAGEB + TILEB) / 2,
                 wm, wn, tgrp, trow, acc);
        __syncthreads();
    }
    // write h2 (bias+relu) into smem as bf16 hi/lo (overwrites phase-A A stages)
#pragma unroll
    for (int mf = 0; mf < 2; mf++)
#pragma unroll
        for (int nf = 0; nf < 8; nf++) {
            int n = wn * 64 + nf * 8 + qcol;
            float bx = __ldg(b2 + n), by = __ldg(b2 + n + 1);
#pragma unroll
            for (int half = 0; half < 2; half++) {
                int row = wm * 32 + mf * 16 + half * 8 + qrow;
                float v0 = fmaxf(acc[mf][nf][half * 2]     + bx, 0.f);
                float v1 = fmaxf(acc[mf][nf][half * 2 + 1] + by, 0.f);
                __nv_bfloat16 h0, l0, h1b, l1b;
                split_bf16(v0, h0, l0);
                split_bf16(v1, h1b, l1b);
                H2h[row * HPAD + n]     = h0;
                H2h[row * HPAD + n + 1] = h1b;
                H2l[row * HPAD + n]     = l0;
                H2l[row * HPAD + n + 1] = l1b;
            }
        }
    __syncthreads();

    // ---- phase B: U[:, y*128..] = h2 @ W3y^T, 8 B-rounds (y = r>>2) ----
    issue_tile(sb, sb + TILEB, g_Wh + 65536, g_Wlo + 65536, 128, 127, 0, t);
    CP_COMMIT();
    for (int r = 0; r < 8; r++) {
        int cur = r & 1, nxt = (r + 1) & 1;
        if ((r & 3) == 0) {
#pragma unroll
            for (int i = 0; i < 2; i++)
#pragma unroll
                for (int j = 0; j < 8; j++)
#pragma unroll
                    for (int k = 0; k < 4; k++) acc[i][j][k] = 0.f;
        }
        if (r + 1 < 8) {
            int nr = r + 1;
            issue_tile(sb + nxt * STAGEB, sb + nxt * STAGEB + TILEB,
                       g_Wh + 65536 + (nr >> 2) * 16384, g_Wlo + 65536 + (nr >> 2) * 16384,
                       128, 127, (nr & 3) * 32, t);
        }
        CP_COMMIT();
        CP_WAIT1();
        __syncthreads();
        mma_step(H2h, H2l, HPAD, (r & 3) * 32,
                 sm + (cur * STAGEB) / 2, sm + (cur * STAGEB + TILEB) / 2,
                 wm, wn, tgrp, trow, acc);
        __syncthreads();
        if ((r & 3) == 3) {
            int y = r >> 2;
#pragma unroll
            for (int mf = 0; mf < 2; mf++)
#pragma unroll
                for (int nf = 0; nf < 8; nf++) {
                    int n = wn * 64 + nf * 8 + qcol;
#pragma unroll
                    for (int half = 0; half < 2; half++) {
                        int gr = m0 + wm * 32 + mf * 16 + half * 8 + qrow;
                        if (gr < M) {
                            *(float2*)(g_U + (size_t)gr * 256 + y * 128 + n) =
                                make_float2(acc[mf][nf][half * 2], acc[mf][nf][half * 2 + 1]);
                        }
                    }
                }
        }
    }
}

// ---------------- pair head: sigmoid(W4 . relu(Ua[a]+Ub[b]+b3) + b4) ----------------
__global__ void __launch_bounds__(256)
pair_kernel(const int* __restrict__ pairs,
            const float* __restrict__ b3, const float* __restrict__ W4,
            const float* __restrict__ b4, float* __restrict__ out, int P) {
    int w    = (blockIdx.x * blockDim.x + threadIdx.x) >> 5;
    int lane = threadIdx.x & 31;
    if (w >= P) return;
    int na = __ldg(&pairs[2 * w]);
    int nb = __ldg(&pairs[2 * w + 1]);
    float4 ua = *((const float4*)(g_U + (size_t)na * 256) + lane);
    float4 ub = *((const float4*)(g_U + (size_t)nb * 256 + 128) + lane);
    float4 bv = *((const float4*)b3 + lane);
    float4 wv = *((const float4*)W4 + lane);
    float s = fmaxf(ua.x + ub.x + bv.x, 0.f) * wv.x
            + fmaxf(ua.y + ub.y + bv.y, 0.f) * wv.y
            + fmaxf(ua.z + ub.z + bv.z, 0.f) * wv.z
            + fmaxf(ua.w + ub.w + bv.w, 0.f) * wv.w;
#pragma unroll
    for (int o = 16; o > 0; o >>= 1)
        s += __shfl_xor_sync(0xffffffffu, s, o);
    if (lane == 0) out[w] = 1.0f / (1.0f + __expf(-(s + b4[0])));
}

// ---------------- launch ----------------
extern "C" void kernel_launch(void* const* d_in, const int* in_sizes, int n_in,
                              void* d_out, int out_size) {
    const float* x    = (const float*)d_in[0];
    const int*   edge = (const int*)d_in[1];
    const int*   prs  = (const int*)d_in[2];
    const float* Wl1  = (const float*)d_in[3];
    const float* Wr1  = (const float*)d_in[4];
    const float* b1   = (const float*)d_in[5];
    const float* Wl2  = (const float*)d_in[6];
    const float* Wr2  = (const float*)d_in[7];
    const float* b2   = (const float*)d_in[8];
    const float* W3   = (const float*)d_in[9];
    const float* b3   = (const float*)d_in[10];
    const float* W4   = (const float*)d_in[11];
    const float* b4   = (const float*)d_in[12];
    float* out = (float*)d_out;

    const int E = in_sizes[1] / 2;
    const int P = in_sizes[2] / 2;
    const int M = N_NODES;
    const int* src = edge;
    const int* dst = edge + E;

    float* g_h1_p;  cudaGetSymbolAddress((void**)&g_h1_p, g_h1);

    cudaFuncSetAttribute(tgemm_kernel,   cudaFuncAttributeMaxDynamicSharedMemorySize, T1_SMEM);
    cudaFuncSetAttribute(layer2u_kernel, cudaFuncAttributeMaxDynamicSharedMemorySize, L2U_SMEM);

    const int aggBlocks = (N_NODES * 32 + 255) / 256;
    const int mTiles = (M + 127) / 128;   // 391

    // CSR build + weight split fused (g_deg zeroed: BSS init / previous scan_deg run)
    countsplit_kernel<<<(E + 255) / 256, 256>>>(dst, E, Wl1, Wr1, Wl2, Wr2, W3);
    scan_deg_kernel<<<1, 1024>>>(E);
    fill_csr_kernel<<<(E + 255) / 256, 256>>>(src, dst, E);

    // Layer 1
    agg_mean_kernel<<<aggBlocks, 256>>>(x, 0);
    tgemm_kernel<<<mTiles, 256, T1_SMEM>>>(x, b1, g_h1_p, M);
    // Layer 2 + U fused (h2 never leaves smem)
    agg_mean_kernel<<<aggBlocks, 256>>>(x, 1);
    layer2u_kernel<<<mTiles, 256, L2U_SMEM>>>(b2, M);
    // Pair head
    pair_kernel<<<(P * 32 + 255) / 256, 256>>>(prs, b3, W4, b4, out, P);
}

// round 16
// speedup vs baseline: 1.1969x; 1.1068x over previous
#include <cuda_runtime.h>
#include <cuda_bf16.h>
#include <math.h>
#include <stdint.h>

#define N_NODES 50000
#define E_EDGES 500000
#define HDIM    128

// ---- scratch (device globals; no allocation in kernel_launch) ----
__device__ int   g_deg[N_NODES];
__device__ int   g_rowstart[N_NODES + 1];
__device__ int   g_cursor[N_NODES];
__device__ int   g_csr_src[E_EDGES];
__device__ float g_h1  [(size_t)N_NODES * HDIM];
__device__ float g_U   [(size_t)N_NODES * 256];
// pre-split operands (bf16 hi/lo)
__device__ __nv_bfloat16 g_aggh[(size_t)N_NODES * HDIM];
__device__ __nv_bfloat16 g_aggl[(size_t)N_NODES * HDIM];
__device__ __nv_bfloat16 g_h1h [(size_t)N_NODES * HDIM];
__device__ __nv_bfloat16 g_h1l [(size_t)N_NODES * HDIM];
// split weights bf16 hi/lo, [n][k] row-major:
// L1 [128][256] @0, L2 [128][256] @32768, W3a [128][128] @65536, W3b [128][128] @81920
__device__ __nv_bfloat16 g_Wh[98304];
__device__ __nv_bfloat16 g_Wlo[98304];

__device__ __forceinline__ uint32_t smem_u32(const void* p) {
    uint32_t a;
    asm("{ .reg .u64 t; cvta.to.shared.u64 t, %1; cvt.u32.u64 %0, t; }" : "=r"(a) : "l"(p));
    return a;
}
#define LDSM_X4(r0, r1, r2, r3, a) \
    asm volatile("ldmatrix.sync.aligned.m8n8.x4.shared.b16 {%0,%1,%2,%3}, [%4];" \
        : "=r"(r0), "=r"(r1), "=r"(r2), "=r"(r3) : "r"(a))
#define MMA_BF16(c, a, b0, b1) \
    asm volatile("mma.sync.aligned.m16n8k16.row.col.f32.bf16.bf16.f32 " \
        "{%0,%1,%2,%3}, {%4,%5,%6,%7}, {%8,%9}, {%0,%1,%2,%3};" \
        : "+f"((c)[0]), "+f"((c)[1]), "+f"((c)[2]), "+f"((c)[3]) \
        : "r"((a)[0]), "r"((a)[1]), "r"((a)[2]), "r"((a)[3]), "r"(b0), "r"(b1))
#define CP16(dst, src) \
    asm volatile("cp.async.ca.shared.global [%0], [%1], 16;" :: "r"(dst), "l"(src))
#define CP_COMMIT() asm volatile("cp.async.commit_group;" ::: "memory")
#define CP_WAIT1()  asm volatile("cp.async.wait_group 1;" ::: "memory")

__device__ __forceinline__ void split_bf16(float v, __nv_bfloat16& h, __nv_bfloat16& l) {
    h = __float2bfloat16(v);
    l = __float2bfloat16(v - __bfloat162float(h));
}
__device__ __forceinline__ uint32_t pack2(__nv_bfloat16 a, __nv_bfloat16 b) {
    return (uint32_t)__bfloat16_as_ushort(a) | ((uint32_t)__bfloat16_as_ushort(b) << 16);
}

// ---------------- CSR build ----------------
__global__ void count_deg_kernel(const int* __restrict__ dst, int E) {
    int i = blockIdx.x * blockDim.x + threadIdx.x;
    if (i < E) atomicAdd(&g_deg[dst[i]], 1);
}

__global__ void scan_deg_kernel(int E) {
    __shared__ int ssum[1024];
    int tid = threadIdx.x;
    const int chunk = (N_NODES + 1023) / 1024;
    int start = tid * chunk;
    int end = min(start + chunk, N_NODES);
    int s = 0;
    for (int i = start; i < end; i++) s += g_deg[i];
    ssum[tid] = s;
    __syncthreads();
    for (int d = 1; d < 1024; d <<= 1) {
        int v = (tid >= d) ? ssum[tid - d] : 0;
        __syncthreads();
        ssum[tid] += v;
        __syncthreads();
    }
    int run = ssum[tid] - s;
    for (int i = start; i < end; i++) {
        g_rowstart[i] = run;
        g_cursor[i]   = run;
        run += g_deg[i];
    }
    if (tid == 1023) g_rowstart[N_NODES] = E;
}

__global__ void fill_csr_kernel(const int* __restrict__ src,
                                const int* __restrict__ dst, int E) {
    int i = blockIdx.x * blockDim.x + threadIdx.x;
    if (i < E) {
        int p = atomicAdd(&g_cursor[dst[i]], 1);
        g_csr_src[p] = src[i];
    }
}

// ---------------- weight split: fp32 -> bf16 hi/lo ----------------
__global__ void split_w_kernel(const float* __restrict__ Wl1, const float* __restrict__ Wr1,
                               const float* __restrict__ Wl2, const float* __restrict__ Wr2,
                               const float* __restrict__ W3) {
    int idx = blockIdx.x * blockDim.x + threadIdx.x;
    if (idx >= 98304) return;
    float v;
    if (idx < 32768) {
        int n = idx >> 8, k = idx & 255;
        v = (k < 128) ? Wl1[n * 128 + k] : Wr1[n * 128 + (k - 128)];
    } else if (idx < 65536) {
        int j = idx - 32768;
        int n = j >> 8, k = j & 255;
        v = (k < 128) ? Wl2[n * 128 + k] : Wr2[n * 128 + (k - 128)];
    } else {
        int j = idx - 65536;
        int half = j >> 14;
        int jj = j & 16383;
        int n = jj >> 7, k = jj & 127;
        v = W3[n * 256 + half * 128 + k];
    }
    __nv_bfloat16 h, l;
    split_bf16(v, h, l);
    g_Wh[idx]  = h;
    g_Wlo[idx] = l;
}

// ---------------- mean aggregation: warp per node, MLP=8; writes split bf16 ----------------
__global__ void agg_mean_kernel(const float* __restrict__ xin, int use_h1) {
    int gw   = (blockIdx.x * blockDim.x + threadIdx.x) >> 5;
    int lane = threadIdx.x & 31;
    if (gw >= N_NODES) return;
    const float* in = use_h1 ? g_h1 : xin;
    int s = g_rowstart[gw];
    int e = g_rowstart[gw + 1];
    float4 a0 = make_float4(0.f, 0.f, 0.f, 0.f);
    float4 a1 = make_float4(0.f, 0.f, 0.f, 0.f);
    float4 a2 = make_float4(0.f, 0.f, 0.f, 0.f);
    float4 a3 = make_float4(0.f, 0.f, 0.f, 0.f);
    int j = s;
    for (; j + 8 <= e; j += 8) {
        int s0 = g_csr_src[j],     s1 = g_csr_src[j + 1];
        int s2 = g_csr_src[j + 2], s3 = g_csr_src[j + 3];
        int s4 = g_csr_src[j + 4], s5 = g_csr_src[j + 5];
        int s6 = g_csr_src[j + 6], s7 = g_csr_src[j + 7];
        float4 v0 = *((const float4*)(in + (size_t)s0 * HDIM) + lane);
        float4 v1 = *((const float4*)(in + (size_t)s1 * HDIM) + lane);
        float4 v2 = *((const float4*)(in + (size_t)s2 * HDIM) + lane);
        float4 v3 = *((const float4*)(in + (size_t)s3 * HDIM) + lane);
        float4 v4 = *((const float4*)(in + (size_t)s4 * HDIM) + lane);
        float4 v5 = *((const float4*)(in + (size_t)s5 * HDIM) + lane);
        float4 v6 = *((const float4*)(in + (size_t)s6 * HDIM) + lane);
        float4 v7 = *((const float4*)(in + (size_t)s7 * HDIM) + lane);
        a0.x += v0.x; a0.y += v0.y; a0.z += v0.z; a0.w += v0.w;
        a1.x += v1.x; a1.y += v1.y; a1.z += v1.z; a1.w += v1.w;
        a2.x += v2.x; a2.y += v2.y; a2.z += v2.z; a2.w += v2.w;
        a3.x += v3.x; a3.y += v3.y; a3.z += v3.z; a3.w += v3.w;
        a0.x += v4.x; a0.y += v4.y; a0.z += v4.z; a0.w += v4.w;
        a1.x += v5.x; a1.y += v5.y; a1.z += v5.z; a1.w += v5.w;
        a2.x += v6.x; a2.y += v6.y; a2.z += v6.z; a2.w += v6.w;
        a3.x += v7.x; a3.y += v7.y; a3.z += v7.z; a3.w += v7.w;
    }
    for (; j + 2 <= e; j += 2) {
        int s0 = g_csr_src[j], s1 = g_csr_src[j + 1];
        float4 v0 = *((const float4*)(in + (size_t)s0 * HDIM) + lane);
        float4 v1 = *((const float4*)(in + (size_t)s1 * HDIM) + lane);
        a0.x += v0.x; a0.y += v0.y; a0.z += v0.z; a0.w += v0.w;
        a1.x += v1.x; a1.y += v1.y; a1.z += v1.z; a1.w += v1.w;
    }
    if (j < e) {
        int s0 = g_csr_src[j];
        float4 v0 = *((const float4*)(in + (size_t)s0 * HDIM) + lane);
        a0.x += v0.x; a0.y += v0.y; a0.z += v0.z; a0.w += v0.w;
    }
    float4 acc;
    acc.x = (a0.x + a1.x) + (a2.x + a3.x);
    acc.y = (a0.y + a1.y) + (a2.y + a3.y);
    acc.z = (a0.z + a1.z) + (a2.z + a3.z);
    acc.w = (a0.w + a1.w) + (a2.w + a3.w);
    float inv = 1.0f / (float)max(e - s, 1);
    acc.x *= inv; acc.y *= inv; acc.z *= inv; acc.w *= inv;
    __nv_bfloat16 h0, l0, h1, l1, h2, l2, h3, l3;
    split_bf16(acc.x, h0, l0); split_bf16(acc.y, h1, l1);
    split_bf16(acc.z, h2, l2); split_bf16(acc.w, h3, l3);
    uint2 hv = make_uint2(pack2(h0, h1), pack2(h2, h3));
    uint2 lv = make_uint2(pack2(l0, l1), pack2(l2, l3));
    *((uint2*)(g_aggh + (size_t)gw * HDIM) + lane) = hv;
    *((uint2*)(g_aggl + (size_t)gw * HDIM) + lane) = lv;
}

// ================= GEMM building blocks =================
// Block: 256 thr (8 warps, 4m x 2n), tile 128x128, BK=32. Warp tile 32x64.
#define APAD 40    // 80B smem row stride, conflict-free ldmatrix, 16B aligned rows
#define HPAD 136   // 272B row stride for h2 smem tile
#define TILEB 10240                       // one 128xAPAD bf16 tile
#define STAGEB (2 * TILEB)                // Ah+Al or Bh+Bl per stage

// cp.async issue of one 128x32 bf16 tile pair (hi/lo), 2x16B per thread each
__device__ __forceinline__ void issue_tile(uint32_t dh, uint32_t dl,
                                           const __nv_bfloat16* sh, const __nv_bfloat16* sl,
                                           size_t rstride, int rclamp, int coff, int t) {
#pragma unroll
    for (int it = 0; it < 2; it++) {
        int q = t + it * 256;
        int row = q >> 2, u = q & 3;
        int gr = min(row, rclamp);
        const __nv_bfloat16* ph = sh + (size_t)gr * rstride + coff + u * 8;
        const __nv_bfloat16* pl = sl + (size_t)gr * rstride + coff + u * 8;
        CP16(dh + row * 80 + u * 16, ph);
        CP16(dl + row * 80 + u * 16, pl);
    }
}

// one BK=32 compute step; A at row-stride lda (elements), B at APAD
__device__ __forceinline__ void mma_step(const __nv_bfloat16* Ah, const __nv_bfloat16* Al, int lda,
                                         int akbase,
                                         const __nv_bfloat16* Bh, const __nv_bfloat16* Bl,
                                         int wm, int wn, int tgrp, int trow,
                                         float acc[2][8][4]) {
#pragma unroll
    for (int ks = 0; ks < 2; ks++) {
        int ak = akbase + ks * 16;
        int bk = ks * 16;
        uint32_t ahf[2][4], alf[2][4];
#pragma unroll
        for (int mf = 0; mf < 2; mf++) {
            int ar = wm * 32 + mf * 16 + (tgrp & 1) * 8 + trow;
            int ac = ak + (tgrp >> 1) * 8;
            LDSM_X4(ahf[mf][0], ahf[mf][1], ahf[mf][2], ahf[mf][3], smem_u32(&Ah[ar * lda + ac]));
            LDSM_X4(alf[mf][0], alf[mf][1], alf[mf][2], alf[mf][3], smem_u32(&Al[ar * lda + ac]));
        }
#pragma unroll
        for (int np = 0; np < 4; np++) {
            int br = wn * 64 + np * 16 + (tgrp >> 1) * 8 + trow;
            int bc = bk + (tgrp & 1) * 8;
            uint32_t bh0, bh1, bh2, bh3, bl0, bl1, bl2, bl3;
            LDSM_X4(bh0, bh1, bh2, bh3, smem_u32(&Bh[br * APAD + bc]));
            LDSM_X4(bl0, bl1, bl2, bl3, smem_u32(&Bl[br * APAD + bc]));
#pragma unroll
            for (int mf = 0; mf < 2; mf++) {
                MMA_BF16(acc[mf][np * 2],     ahf[mf], bh0, bh1);
                MMA_BF16(acc[mf][np * 2],     ahf[mf], bl0, bl1);
                MMA_BF16(acc[mf][np * 2],     alf[mf], bh0, bh1);
                MMA_BF16(acc[mf][np * 2 + 1], ahf[mf], bh2, bh3);
                MMA_BF16(acc[mf][np * 2 + 1], ahf[mf], bl2, bl3);
                MMA_BF16(acc[mf][np * 2 + 1], alf[mf], bh2, bh3);
            }
        }
    }
}

// ---------------- layer-1 GEMM: h1 = relu([agg|x] @ [Wl1|Wr1]^T + b1) ----------------
// dyn smem: B stages [0,2*STAGEB) | A stages [2*STAGEB, 4*STAGEB)  = 81920 B
#define T1_SMEM (4 * STAGEB)
__global__ void __launch_bounds__(256)
tgemm_kernel(const float* __restrict__ x, const float* __restrict__ bias,
             float* __restrict__ outp, int M) {
    extern __shared__ __nv_bfloat16 sm[];
    uint32_t sb = smem_u32(sm);
    int t = threadIdx.x, lane = t & 31, wid = t >> 5;
    int wm = wid >> 1, wn = wid & 1;
    int m0 = blockIdx.x * 128;
    int rclamp = M - 1 - m0;
    int tgrp = lane >> 3, trow = lane & 7;

    float acc[2][8][4];
#pragma unroll
    for (int i = 0; i < 2; i++)
#pragma unroll
        for (int j = 0; j < 8; j++)
#pragma unroll
            for (int k = 0; k < 4; k++) acc[i][j][k] = 0.f;

    const __nv_bfloat16* aggh = g_aggh + (size_t)m0 * HDIM;
    const __nv_bfloat16* aggl = g_aggl + (size_t)m0 * HDIM;

    issue_tile(sb + 2 * STAGEB, sb + 2 * STAGEB + TILEB, aggh, aggl, HDIM, rclamp, 0, t);
    issue_tile(sb, sb + TILEB, g_Wh, g_Wlo, 256, 127, 0, t);
    CP_COMMIT();

    for (int ch = 0; ch < 8; ch++) {
        int cur = ch & 1, nxt = (ch + 1) & 1;
        float4 xr[4];
        bool havex = false;
        if (ch + 1 < 8) {
            int nc = ch + 1;
            int acol = (nc & 3) * 32;
            if (nc < 4) {
                issue_tile(sb + 2 * STAGEB + nxt * STAGEB, sb + 2 * STAGEB + nxt * STAGEB + TILEB,
                           aggh, aggl, HDIM, rclamp, acol, t);
            } else {
#pragma unroll
                for (int it = 0; it < 2; it++) {
                    int q = t + it * 256;
                    int row = q >> 2, u = q & 3;
                    int gr = min(m0 + row, M - 1);
                    const float4* p = (const float4*)(x + (size_t)gr * HDIM + acol + u * 8);
                    xr[it * 2]     = p[0];
                    xr[it * 2 + 1] = p[1];
                }
                havex = true;
            }
            issue_tile(sb + nxt * STAGEB, sb + nxt * STAGEB + TILEB, g_Wh, g_Wlo, 256, 127, nc * 32, t);
        }
        CP_COMMIT();
        CP_WAIT1();
        __syncthreads();
        mma_step(sm + (2 * STAGEB + cur * STAGEB) / 2, sm + (2 * STAGEB + cur * STAGEB + TILEB) / 2,
                 APAD, 0,
                 sm + (cur * STAGEB) / 2, sm + (cur * STAGEB + TILEB) / 2,
                 wm, wn, tgrp, trow, acc);
        __syncthreads();
        if (havex) {
            __nv_bfloat16* Ahn = sm + (2 * STAGEB + nxt * STAGEB) / 2;
            __nv_bfloat16* Aln = Ahn + TILEB / 2;
#pragma unroll
            for (int it = 0; it < 2; it++) {
                int q = t + it * 256;
                int row = q >> 2, u = q & 3;
                const float* f = (const float*)&xr[it * 2];
                __nv_bfloat16 hh[8], ll[8];
#pragma unroll
                for (int i = 0; i < 8; i++) split_bf16(f[i], hh[i], ll[i]);
                uint4 hv = make_uint4(pack2(hh[0], hh[1]), pack2(hh[2], hh[3]),
                                      pack2(hh[4], hh[5]), pack2(hh[6], hh[7]));
                uint4 lv = make_uint4(pack2(ll[0], ll[1]), pack2(ll[2], ll[3]),
                                      pack2(ll[4], ll[5]), pack2(ll[6], ll[7]));
                *(uint4*)&Ahn[row * APAD + u * 8] = hv;
                *(uint4*)&Aln[row * APAD + u * 8] = lv;
            }
        }
    }
    // epilogue: bias+relu -> h1 fp32 AND pre-split bf16
    int qrow = lane >> 2, qcol = (lane & 3) * 2;
#pragma unroll
    for (int mf = 0; mf < 2; mf++)
#pragma unroll
        for (int nf = 0; nf < 8; nf++) {
            int n = wn * 64 + nf * 8 + qcol;
            float bx = __ldg(bias + n), by = __ldg(bias + n + 1);
#pragma unroll
            for (int half = 0; half < 2; half++) {
                int gr = m0 + wm * 32 + mf * 16 + half * 8 + qrow;
                if (gr < M) {
                    float v0 = fmaxf(acc[mf][nf][half * 2]     + bx, 0.f);
                    float v1 = fmaxf(acc[mf][nf][half * 2 + 1] + by, 0.f);
                    *(float2*)(outp + (size_t)gr * HDIM + n) = make_float2(v0, v1);
                    __nv_bfloat16 h0, l0, h1b, l1b;
                    split_bf16(v0, h0, l0);
                    split_bf16(v1, h1b, l1b);
                    *(uint32_t*)(g_h1h + (size_t)gr * HDIM + n) = pack2(h0, h1b);
                    *(uint32_t*)(g_h1l + (size_t)gr * HDIM + n) = pack2(l0, l1b);
                }
            }
        }
}

// ---------------- fused layer-2 + U: h2 stays in smem ----------------
#define L2U_SMEM (2 * STAGEB + 2 * 128 * HPAD * 2)   // 110592 B
__global__ void __launch_bounds__(256)
layer2u_kernel(const float* __restrict__ b2, int M) {
    extern __shared__ __nv_bfloat16 sm[];
    uint32_t sb = smem_u32(sm);
    const uint32_t XOFF = 2 * STAGEB;
    __nv_bfloat16* H2h = sm + XOFF / 2;
    __nv_bfloat16* H2l = H2h + 128 * HPAD;

    int t = threadIdx.x, lane = t & 31, wid = t >> 5;
    int wm = wid >> 1, wn = wid & 1;
    int m0 = blockIdx.x * 128;
    int rclamp = M - 1 - m0;
    int tgrp = lane >> 3, trow = lane & 7;
    int qrow = lane >> 2, qcol = (lane & 3) * 2;

    float acc[2][8][4];
#pragma unroll
    for (int i = 0; i < 2; i++)
#pragma unroll
        for (int j = 0; j < 8; j++)
#pragma unroll
            for (int k = 0; k < 4; k++) acc[i][j][k] = 0.f;

    const __nv_bfloat16* a0h = g_aggh + (size_t)m0 * HDIM;
    const __nv_bfloat16* a0l = g_aggl + (size_t)m0 * HDIM;
    const __nv_bfloat16* a1h = g_h1h + (size_t)m0 * HDIM;
    const __nv_bfloat16* a1l = g_h1l + (size_t)m0 * HDIM;

    // ---- phase A: h2 = relu([agg|h1] @ [Wl2|Wr2]^T + b2) ----
    issue_tile(sb + XOFF, sb + XOFF + TILEB, a0h, a0l, HDIM, rclamp, 0, t);
    issue_tile(sb, sb + TILEB, g_Wh + 32768, g_Wlo + 32768, 256, 127, 0, t);
    CP_COMMIT();
    for (int ch = 0; ch < 8; ch++) {
        int cur = ch & 1, nxt = (ch + 1) & 1;
        if (ch + 1 < 8) {
            int nc = ch + 1;
            const __nv_bfloat16* sh = (nc < 4) ? a0h : a1h;
            const __nv_bfloat16* sl = (nc < 4) ? a0l : a1l;
            issue_tile(sb + XOFF + nxt * STAGEB, sb + XOFF + nxt * STAGEB + TILEB,
                       sh, sl, HDIM, rclamp, (nc & 3) * 32, t);
            issue_tile(sb + nxt * STAGEB, sb + nxt * STAGEB + TILEB,
                       g_Wh + 32768, g_Wlo + 32768, 256, 127, nc * 32, t);
        }
        CP_COMMIT();
        CP_WAIT1();
        __syncthreads();
        mma_step(sm + (XOFF + cur * STAGEB) / 2, sm + (XOFF + cur * STAGEB + TILEB) / 2,
                 APAD, 0,
                 sm + (cur * STAGEB) / 2, sm + (cur * STAGEB + TILEB) / 2,
                 wm, wn, tgrp, trow, acc);
        __syncthreads();
    }
    // write h2 (bias+relu) into smem as bf16 hi/lo (overwrites phase-A A stages)
#pragma unroll
    for (int mf = 0; mf < 2; mf++)
#pragma unroll
        for (int nf = 0; nf < 8; nf++) {
            int n = wn * 64 + nf * 8 + qcol;
            float bx = __ldg(b2 + n), by = __ldg(b2 + n + 1);
#pragma unroll
            for (int half = 0; half < 2; half++) {
                int row = wm * 32 + mf * 16 + half * 8 + qrow;
                float v0 = fmaxf(acc[mf][nf][half * 2]     + bx, 0.f);
                float v1 = fmaxf(acc[mf][nf][half * 2 + 1] + by, 0.f);
                __nv_bfloat16 h0, l0, h1b, l1b;
                split_bf16(v0, h0, l0);
                split_bf16(v1, h1b, l1b);
                H2h[row * HPAD + n]     = h0;
                H2h[row * HPAD + n + 1] = h1b;
                H2l[row * HPAD + n]     = l0;
                H2l[row * HPAD + n + 1] = l1b;
            }
        }
    __syncthreads();

    // ---- phase B: U[:, y*128..] = h2 @ W3y^T, 8 B-rounds (y = r>>2) ----
    issue_tile(sb, sb + TILEB, g_Wh + 65536, g_Wlo + 65536, 128, 127, 0, t);
    CP_COMMIT();
    for (int r = 0; r < 8; r++) {
        int cur = r & 1, nxt = (r + 1) & 1;
        if ((r & 3) == 0) {
#pragma unroll
            for (int i = 0; i < 2; i++)
#pragma unroll
                for (int j = 0; j < 8; j++)
#pragma unroll
                    for (int k = 0; k < 4; k++) acc[i][j][k] = 0.f;
        }
        if (r + 1 < 8) {
            int nr = r + 1;
            issue_tile(sb + nxt * STAGEB, sb + nxt * STAGEB + TILEB,
                       g_Wh + 65536 + (nr >> 2) * 16384, g_Wlo + 65536 + (nr >> 2) * 16384,
                       128, 127, (nr & 3) * 32, t);
        }
        CP_COMMIT();
        CP_WAIT1();
        __syncthreads();
        mma_step(H2h, H2l, HPAD, (r & 3) * 32,
                 sm + (cur * STAGEB) / 2, sm + (cur * STAGEB + TILEB) / 2,
                 wm, wn, tgrp, trow, acc);
        __syncthreads();
        if ((r & 3) == 3) {
            int y = r >> 2;
#pragma unroll
            for (int mf = 0; mf < 2; mf++)
#pragma unroll
                for (int nf = 0; nf < 8; nf++) {
                    int n = wn * 64 + nf * 8 + qcol;
#pragma unroll
                    for (int half = 0; half < 2; half++) {
                        int gr = m0 + wm * 32 + mf * 16 + half * 8 + qrow;
                        if (gr < M) {
                            *(float2*)(g_U + (size_t)gr * 256 + y * 128 + n) =
                                make_float2(acc[mf][nf][half * 2], acc[mf][nf][half * 2 + 1]);
                        }
                    }
                }
        }
    }
}

// ---------------- pair head: sigmoid(W4 . relu(Ua[a]+Ub[b]+b3) + b4) ----------------
__global__ void __launch_bounds__(256)
pair_kernel(const int* __restrict__ pairs,
            const float* __restrict__ b3, const float* __restrict__ W4,
            const float* __restrict__ b4, float* __restrict__ out, int P) {
    int w    = (blockIdx.x * blockDim.x + threadIdx.x) >> 5;
    int lane = threadIdx.x & 31;
    if (w >= P) return;
    int na = __ldg(&pairs[2 * w]);
    int nb = __ldg(&pairs[2 * w + 1]);
    float4 ua = *((const float4*)(g_U + (size_t)na * 256) + lane);
    float4 ub = *((const float4*)(g_U + (size_t)nb * 256 + 128) + lane);
    float4 bv = *((const float4*)b3 + lane);
    float4 wv = *((const float4*)W4 + lane);
    float s = fmaxf(ua.x + ub.x + bv.x, 0.f) * wv.x
            + fmaxf(ua.y + ub.y + bv.y, 0.f) * wv.y
            + fmaxf(ua.z + ub.z + bv.z, 0.f) * wv.z
            + fmaxf(ua.w + ub.w + bv.w, 0.f) * wv.w;
#pragma unroll
    for (int o = 16; o > 0; o >>= 1)
        s += __shfl_xor_sync(0xffffffffu, s, o);
    if (lane == 0) out[w] = 1.0f / (1.0f + __expf(-(s + b4[0])));
}

// ---------------- launch ----------------
extern "C" void kernel_launch(void* const* d_in, const int* in_sizes, int n_in,
                              void* d_out, int out_size) {
    const float* x    = (const float*)d_in[0];
    const int*   edge = (const int*)d_in[1];
    const int*   prs  = (const int*)d_in[2];
    const float* Wl1  = (const float*)d_in[3];
    const float* Wr1  = (const float*)d_in[4];
    const float* b1   = (const float*)d_in[5];
    const float* Wl2  = (const float*)d_in[6];
    const float* Wr2  = (const float*)d_in[7];
    const float* b2   = (const float*)d_in[8];
    const float* W3   = (const float*)d_in[9];
    const float* b3   = (const float*)d_in[10];
    const float* W4   = (const float*)d_in[11];
    const float* b4   = (const float*)d_in[12];
    float* out = (float*)d_out;

    const int E = in_sizes[1] / 2;
    const int P = in_sizes[2] / 2;
    const int M = N_NODES;
    const int* src = edge;
    const int* dst = edge + E;

    float* g_h1_p;  cudaGetSymbolAddress((void**)&g_h1_p, g_h1);
    int*   g_deg_p; cudaGetSymbolAddress((void**)&g_deg_p, g_deg);

    cudaFuncSetAttribute(tgemm_kernel,   cudaFuncAttributeMaxDynamicSharedMemorySize, T1_SMEM);
    cudaFuncSetAttribute(layer2u_kernel, cudaFuncAttributeMaxDynamicSharedMemorySize, L2U_SMEM);

    // weight split + CSR build
    split_w_kernel<<<(98304 + 255) / 256, 256>>>(Wl1, Wr1, Wl2, Wr2, W3);
    cudaMemsetAsync(g_deg_p, 0, N_NODES * sizeof(int));
    count_deg_kernel<<<(E + 255) / 256, 256>>>(dst, E);
    scan_deg_kernel<<<1, 1024>>>(E);
    fill_csr_kernel<<<(E + 255) / 256, 256>>>(src, dst, E);

    const int aggBlocks = (N_NODES * 32 + 255) / 256;
    const int mTiles = (M + 127) / 128;   // 391

    // Layer 1
    agg_mean_kernel<<<aggBlocks, 256>>>(x, 0);
    tgemm_kernel<<<mTiles, 256, T1_SMEM>>>(x, b1, g_h1_p, M);
    // Layer 2 + U fused (h2 never leaves smem)
    agg_mean_kernel<<<aggBlocks, 256>>>(x, 1);
    layer2u_kernel<<<mTiles, 256, L2U_SMEM>>>(b2, M);
    // Pair head
    pair_kernel<<<(P * 32 + 255) / 256, 256>>>(prs, b3, W4, b4, out, P);
}

// round 17
// speedup vs baseline: 1.2143x; 1.0145x over previous
#include <cuda_runtime.h>
#include <cuda_bf16.h>
#include <math.h>
#include <stdint.h>

#define N_NODES 50000
#define E_EDGES 500000
#define HDIM    128

// ---- scratch (device globals; no allocation in kernel_launch) ----
__device__ int   g_deg[N_NODES];
__device__ int   g_rowstart[N_NODES + 1];
__device__ int   g_cursor[N_NODES];
__device__ int   g_csr_src[E_EDGES];
__device__ float g_h1  [(size_t)N_NODES * HDIM];
__device__ float g_U   [(size_t)N_NODES * 256];
// pre-split operands (bf16 hi/lo)
__device__ __nv_bfloat16 g_aggh[(size_t)N_NODES * HDIM];
__device__ __nv_bfloat16 g_aggl[(size_t)N_NODES * HDIM];
__device__ __nv_bfloat16 g_h1h [(size_t)N_NODES * HDIM];
__device__ __nv_bfloat16 g_h1l [(size_t)N_NODES * HDIM];
// split weights bf16 hi/lo, [n][k] row-major:
// L1 [128][256] @0, L2 [128][256] @32768, W3a [128][128] @65536, W3b [128][128] @81920
__device__ __nv_bfloat16 g_Wh[98304];
__device__ __nv_bfloat16 g_Wlo[98304];

__device__ __forceinline__ uint32_t smem_u32(const void* p) {
    uint32_t a;
    asm("{ .reg .u64 t; cvta.to.shared.u64 t, %1; cvt.u32.u64 %0, t; }" : "=r"(a) : "l"(p));
    return a;
}
#define LDSM_X4(r0, r1, r2, r3, a) \
    asm volatile("ldmatrix.sync.aligned.m8n8.x4.shared.b16 {%0,%1,%2,%3}, [%4];" \
        : "=r"(r0), "=r"(r1), "=r"(r2), "=r"(r3) : "r"(a))
#define MMA_BF16(c, a, b0, b1) \
    asm volatile("mma.sync.aligned.m16n8k16.row.col.f32.bf16.bf16.f32 " \
        "{%0,%1,%2,%3}, {%4,%5,%6,%7}, {%8,%9}, {%0,%1,%2,%3};" \
        : "+f"((c)[0]), "+f"((c)[1]), "+f"((c)[2]), "+f"((c)[3]) \
        : "r"((a)[0]), "r"((a)[1]), "r"((a)[2]), "r"((a)[3]), "r"(b0), "r"(b1))
#define CP16(dst, src) \
    asm volatile("cp.async.ca.shared.global [%0], [%1], 16;" :: "r"(dst), "l"(src))
#define CP_COMMIT() asm volatile("cp.async.commit_group;" ::: "memory")
#define CP_WAIT1()  asm volatile("cp.async.wait_group 1;" ::: "memory")

__device__ __forceinline__ void split_bf16(float v, __nv_bfloat16& h, __nv_bfloat16& l) {
    h = __float2bfloat16(v);
    l = __float2bfloat16(v - __bfloat162float(h));
}
__device__ __forceinline__ uint32_t pack2(__nv_bfloat16 a, __nv_bfloat16 b) {
    return (uint32_t)__bfloat16_as_ushort(a) | ((uint32_t)__bfloat16_as_ushort(b) << 16);
}

// ---------------- CSR build ----------------
__global__ void count_deg_kernel(const int* __restrict__ dst, int E) {
    int i = blockIdx.x * blockDim.x + threadIdx.x;
    if (i < E) atomicAdd(&g_deg[dst[i]], 1);
}

__global__ void scan_deg_kernel(int E) {
    __shared__ int ssum[1024];
    int tid = threadIdx.x;
    const int chunk = (N_NODES + 1023) / 1024;
    int start = tid * chunk;
    int end = min(start + chunk, N_NODES);
    int s = 0;
    for (int i = start; i < end; i++) s += g_deg[i];
    ssum[tid] = s;
    __syncthreads();
    for (int d = 1; d < 1024; d <<= 1) {
        int v = (tid >= d) ? ssum[tid - d] : 0;
        __syncthreads();
        ssum[tid] += v;
        __syncthreads();
    }
    int run = ssum[tid] - s;
    for (int i = start; i < end; i++) {
        g_rowstart[i] = run;
        g_cursor[i]   = run;
        run += g_deg[i];
    }
    if (tid == 1023) g_rowstart[N_NODES] = E;
}

__global__ void fill_csr_kernel(const int* __restrict__ src,
                                const int* __restrict__ dst, int E) {
    int i = blockIdx.x * blockDim.x + threadIdx.x;
    if (i < E) {
        int p = atomicAdd(&g_cursor[dst[i]], 1);
        g_csr_src[p] = src[i];
    }
}

// ---------------- weight split: fp32 -> bf16 hi/lo ----------------
__global__ void split_w_kernel(const float* __restrict__ Wl1, const float* __restrict__ Wr1,
                               const float* __restrict__ Wl2, const float* __restrict__ Wr2,
                               const float* __restrict__ W3) {
    int idx = blockIdx.x * blockDim.x + threadIdx.x;
    if (idx >= 98304) return;
    float v;
    if (idx < 32768) {
        int n = idx >> 8, k = idx & 255;
        v = (k < 128) ? Wl1[n * 128 + k] : Wr1[n * 128 + (k - 128)];
    } else if (idx < 65536) {
        int j = idx - 32768;
        int n = j >> 8, k = j & 255;
        v = (k < 128) ? Wl2[n * 128 + k] : Wr2[n * 128 + (k - 128)];
    } else {
        int j = idx - 65536;
        int half = j >> 14;
        int jj = j & 16383;
        int n = jj >> 7, k = jj & 127;
        v = W3[n * 256 + half * 128 + k];
    }
    __nv_bfloat16 h, l;
    split_bf16(v, h, l);
    g_Wh[idx]  = h;
    g_Wlo[idx] = l;
}

// ---------------- mean aggregation: persistent warps, MLP=8; writes split bf16 ----------------
#define AGG_BLOCKS 1184   // ~2 resident waves at 6 blocks/SM on 148 SMs
__global__ void agg_mean_kernel(const float* __restrict__ xin, int use_h1) {
    int wglob = (blockIdx.x * blockDim.x + threadIdx.x) >> 5;
    int lane  = threadIdx.x & 31;
    const int nwarps = (AGG_BLOCKS * 256) >> 5;
    const float* in = use_h1 ? g_h1 : xin;
    for (int gw = wglob; gw < N_NODES; gw += nwarps) {
        int s = g_rowstart[gw];
        int e = g_rowstart[gw + 1];
        float4 a0 = make_float4(0.f, 0.f, 0.f, 0.f);
        float4 a1 = make_float4(0.f, 0.f, 0.f, 0.f);
        float4 a2 = make_float4(0.f, 0.f, 0.f, 0.f);
        float4 a3 = make_float4(0.f, 0.f, 0.f, 0.f);
        int j = s;
        for (; j + 8 <= e; j += 8) {
            int s0 = g_csr_src[j],     s1 = g_csr_src[j + 1];
            int s2 = g_csr_src[j + 2], s3 = g_csr_src[j + 3];
            int s4 = g_csr_src[j + 4], s5 = g_csr_src[j + 5];
            int s6 = g_csr_src[j + 6], s7 = g_csr_src[j + 7];
            float4 v0 = *((const float4*)(in + (size_t)s0 * HDIM) + lane);
            float4 v1 = *((const float4*)(in + (size_t)s1 * HDIM) + lane);
            float4 v2 = *((const float4*)(in + (size_t)s2 * HDIM) + lane);
            float4 v3 = *((const float4*)(in + (size_t)s3 * HDIM) + lane);
            float4 v4 = *((const float4*)(in + (size_t)s4 * HDIM) + lane);
            float4 v5 = *((const float4*)(in + (size_t)s5 * HDIM) + lane);
            float4 v6 = *((const float4*)(in + (size_t)s6 * HDIM) + lane);
            float4 v7 = *((const float4*)(in + (size_t)s7 * HDIM) + lane);
            a0.x += v0.x; a0.y += v0.y; a0.z += v0.z; a0.w += v0.w;
            a1.x += v1.x; a1.y += v1.y; a1.z += v1.z; a1.w += v1.w;
            a2.x += v2.x; a2.y += v2.y; a2.z += v2.z; a2.w += v2.w;
            a3.x += v3.x; a3.y += v3.y; a3.z += v3.z; a3.w += v3.w;
            a0.x += v4.x; a0.y += v4.y; a0.z += v4.z; a0.w += v4.w;
            a1.x += v5.x; a1.y += v5.y; a1.z += v5.z; a1.w += v5.w;
            a2.x += v6.x; a2.y += v6.y; a2.z += v6.z; a2.w += v6.w;
            a3.x += v7.x; a3.y += v7.y; a3.z += v7.z; a3.w += v7.w;
        }
        for (; j + 2 <= e; j += 2) {
            int s0 = g_csr_src[j], s1 = g_csr_src[j + 1];
            float4 v0 = *((const float4*)(in + (size_t)s0 * HDIM) + lane);
            float4 v1 = *((const float4*)(in + (size_t)s1 * HDIM) + lane);
            a0.x += v0.x; a0.y += v0.y; a0.z += v0.z; a0.w += v0.w;
            a1.x += v1.x; a1.y += v1.y; a1.z += v1.z; a1.w += v1.w;
        }
        if (j < e) {
            int s0 = g_csr_src[j];
            float4 v0 = *((const float4*)(in + (size_t)s0 * HDIM) + lane);
            a0.x += v0.x; a0.y += v0.y; a0.z += v0.z; a0.w += v0.w;
        }
        float4 acc;
        acc.x = (a0.x + a1.x) + (a2.x + a3.x);
        acc.y = (a0.y + a1.y) + (a2.y + a3.y);
        acc.z = (a0.z + a1.z) + (a2.z + a3.z);
        acc.w = (a0.w + a1.w) + (a2.w + a3.w);
        float inv = 1.0f / (float)max(e - s, 1);
        acc.x *= inv; acc.y *= inv; acc.z *= inv; acc.w *= inv;
        __nv_bfloat16 h0, l0, h1, l1, h2, l2, h3, l3;
        split_bf16(acc.x, h0, l0); split_bf16(acc.y, h1, l1);
        split_bf16(acc.z, h2, l2); split_bf16(acc.w, h3, l3);
        uint2 hv = make_uint2(pack2(h0, h1), pack2(h2, h3));
        uint2 lv = make_uint2(pack2(l0, l1), pack2(l2, l3));
        *((uint2*)(g_aggh + (size_t)gw * HDIM) + lane) = hv;
        *((uint2*)(g_aggl + (size_t)gw * HDIM) + lane) = lv;
    }
}

// ================= GEMM building blocks =================
// Block: 256 thr (8 warps, 4m x 2n), tile 128x128, BK=32. Warp tile 32x64.
#define APAD 40    // 80B smem row stride, conflict-free ldmatrix, 16B aligned rows
#define HPAD 136   // 272B row stride for h2 smem tile
#define TILEB 10240                       // one 128xAPAD bf16 tile
#define STAGEB (2 * TILEB)                // Ah+Al or Bh+Bl per stage

// cp.async issue of one 128x32 bf16 tile pair (hi/lo), 2x16B per thread each
__device__ __forceinline__ void issue_tile(uint32_t dh, uint32_t dl,
                                           const __nv_bfloat16* sh, const __nv_bfloat16* sl,
                                           size_t rstride, int rclamp, int coff, int t) {
#pragma unroll
    for (int it = 0; it < 2; it++) {
        int q = t + it * 256;
        int row = q >> 2, u = q & 3;
        int gr = min(row, rclamp);
        const __nv_bfloat16* ph = sh + (size_t)gr * rstride + coff + u * 8;
        const __nv_bfloat16* pl = sl + (size_t)gr * rstride + coff + u * 8;
        CP16(dh + row * 80 + u * 16, ph);
        CP16(dl + row * 80 + u * 16, pl);
    }
}

// one BK=32 compute step; A at row-stride lda (elements), B at APAD
__device__ __forceinline__ void mma_step(const __nv_bfloat16* Ah, const __nv_bfloat16* Al, int lda,
                                         int akbase,
                                         const __nv_bfloat16* Bh, const __nv_bfloat16* Bl,
                                         int wm, int wn, int tgrp, int trow,
                                         float acc[2][8][4]) {
#pragma unroll
    for (int ks = 0; ks < 2; ks++) {
        int ak = akbase + ks * 16;
        int bk = ks * 16;
        uint32_t ahf[2][4], alf[2][4];
#pragma unroll
        for (int mf = 0; mf < 2; mf++) {
            int ar = wm * 32 + mf * 16 + (tgrp & 1) * 8 + trow;
            int ac = ak + (tgrp >> 1) * 8;
            LDSM_X4(ahf[mf][0], ahf[mf][1], ahf[mf][2], ahf[mf][3], smem_u32(&Ah[ar * lda + ac]));
            LDSM_X4(alf[mf][0], alf[mf][1], alf[mf][2], alf[mf][3], smem_u32(&Al[ar * lda + ac]));
        }
#pragma unroll
        for (int np = 0; np < 4; np++) {
            int br = wn * 64 + np * 16 + (tgrp >> 1) * 8 + trow;
            int bc = bk + (tgrp & 1) * 8;
            uint32_t bh0, bh1, bh2, bh3, bl0, bl1, bl2, bl3;
            LDSM_X4(bh0, bh1, bh2, bh3, smem_u32(&Bh[br * APAD + bc]));
            LDSM_X4(bl0, bl1, bl2, bl3, smem_u32(&Bl[br * APAD + bc]));
#pragma unroll
            for (int mf = 0; mf < 2; mf++) {
                MMA_BF16(acc[mf][np * 2],     ahf[mf], bh0, bh1);
                MMA_BF16(acc[mf][np * 2],     ahf[mf], bl0, bl1);
                MMA_BF16(acc[mf][np * 2],     alf[mf], bh0, bh1);
                MMA_BF16(acc[mf][np * 2 + 1], ahf[mf], bh2, bh3);
                MMA_BF16(acc[mf][np * 2 + 1], ahf[mf], bl2, bl3);
                MMA_BF16(acc[mf][np * 2 + 1], alf[mf], bh2, bh3);
            }
        }
    }
}

// ---------------- layer-1 GEMM: h1 = relu([agg|x] @ [Wl1|Wr1]^T + b1) ----------------
// dyn smem: B stages [0,2*STAGEB) | A stages [2*STAGEB, 4*STAGEB)  = 81920 B
#define T1_SMEM (4 * STAGEB)
__global__ void __launch_bounds__(256)
tgemm_kernel(const float* __restrict__ x, const float* __restrict__ bias,
             float* __restrict__ outp, int M) {
    extern __shared__ __nv_bfloat16 sm[];
    uint32_t sb = smem_u32(sm);
    int t = threadIdx.x, lane = t & 31, wid = t >> 5;
    int wm = wid >> 1, wn = wid & 1;
    int m0 = blockIdx.x * 128;
    int rclamp = M - 1 - m0;
    int tgrp = lane >> 3, trow = lane & 7;

    float acc[2][8][4];
#pragma unroll
    for (int i = 0; i < 2; i++)
#pragma unroll
        for (int j = 0; j < 8; j++)
#pragma unroll
            for (int k = 0; k < 4; k++) acc[i][j][k] = 0.f;

    const __nv_bfloat16* aggh = g_aggh + (size_t)m0 * HDIM;
    const __nv_bfloat16* aggl = g_aggl + (size_t)m0 * HDIM;

    issue_tile(sb + 2 * STAGEB, sb + 2 * STAGEB + TILEB, aggh, aggl, HDIM, rclamp, 0, t);
    issue_tile(sb, sb + TILEB, g_Wh, g_Wlo, 256, 127, 0, t);
    CP_COMMIT();

    for (int ch = 0; ch < 8; ch++) {
        int cur = ch & 1, nxt = (ch + 1) & 1;
        float4 xr[4];
        bool havex = false;
        if (ch + 1 < 8) {
            int nc = ch + 1;
            int acol = (nc & 3) * 32;
            if (nc < 4) {
                issue_tile(sb + 2 * STAGEB + nxt * STAGEB, sb + 2 * STAGEB + nxt * STAGEB + TILEB,
                           aggh, aggl, HDIM, rclamp, acol, t);
            } else {
#pragma unroll
                for (int it = 0; it < 2; it++) {
                    int q = t + it * 256;
                    int row = q >> 2, u = q & 3;
                    int gr = min(m0 + row, M - 1);
                    const float4* p = (const float4*)(x + (size_t)gr * HDIM + acol + u * 8);
                    xr[it * 2]     = p[0];
                    xr[it * 2 + 1] = p[1];
                }
                havex = true;
            }
            issue_tile(sb + nxt * STAGEB, sb + nxt * STAGEB + TILEB, g_Wh, g_Wlo, 256, 127, nc * 32, t);
        }
        CP_COMMIT();
        CP_WAIT1();
        __syncthreads();
        mma_step(sm + (2 * STAGEB + cur * STAGEB) / 2, sm + (2 * STAGEB + cur * STAGEB + TILEB) / 2,
                 APAD, 0,
                 sm + (cur * STAGEB) / 2, sm + (cur * STAGEB + TILEB) / 2,
                 wm, wn, tgrp, trow, acc);
        __syncthreads();
        if (havex) {
            __nv_bfloat16* Ahn = sm + (2 * STAGEB + nxt * STAGEB) / 2;
            __nv_bfloat16* Aln = Ahn + TILEB / 2;
#pragma unroll
            for (int it = 0; it < 2; it++) {
                int q = t + it * 256;
                int row = q >> 2, u = q & 3;
                const float* f = (const float*)&xr[it * 2];
                __nv_bfloat16 hh[8], ll[8];
#pragma unroll
                for (int i = 0; i < 8; i++) split_bf16(f[i], hh[i], ll[i]);
                uint4 hv = make_uint4(pack2(hh[0], hh[1]), pack2(hh[2], hh[3]),
                                      pack2(hh[4], hh[5]), pack2(hh[6], hh[7]));
                uint4 lv = make_uint4(pack2(ll[0], ll[1]), pack2(ll[2], ll[3]),
                                      pack2(ll[4], ll[5]), pack2(ll[6], ll[7]));
                *(uint4*)&Ahn[row * APAD + u * 8] = hv;
                *(uint4*)&Aln[row * APAD + u * 8] = lv;
            }
        }
    }
    // epilogue: bias+relu -> h1 fp32 AND pre-split bf16
    int qrow = lane >> 2, qcol = (lane & 3) * 2;
#pragma unroll
    for (int mf = 0; mf < 2; mf++)
#pragma unroll
        for (int nf = 0; nf < 8; nf++) {
            int n = wn * 64 + nf * 8 + qcol;
            float bx = __ldg(bias + n), by = __ldg(bias + n + 1);
#pragma unroll
            for (int half = 0; half < 2; half++) {
                int gr = m0 + wm * 32 + mf * 16 + half * 8 + qrow;
                if (gr < M) {
                    float v0 = fmaxf(acc[mf][nf][half * 2]     + bx, 0.f);
                    float v1 = fmaxf(acc[mf][nf][half * 2 + 1] + by, 0.f);
                    *(float2*)(outp + (size_t)gr * HDIM + n) = make_float2(v0, v1);
                    __nv_bfloat16 h0, l0, h1b, l1b;
                    split_bf16(v0, h0, l0);
                    split_bf16(v1, h1b, l1b);
                    *(uint32_t*)(g_h1h + (size_t)gr * HDIM + n) = pack2(h0, h1b);
                    *(uint32_t*)(g_h1l + (size_t)gr * HDIM + n) = pack2(l0, l1b);
                }
            }
        }
}

// ---------------- fused layer-2 + U: h2 stays in smem ----------------
#define L2U_SMEM (2 * STAGEB + 2 * 128 * HPAD * 2)   // 110592 B
__global__ void __launch_bounds__(256)
layer2u_kernel(const float* __restrict__ b2, int M) {
    extern __shared__ __nv_bfloat16 sm[];
    uint32_t sb = smem_u32(sm);
    const uint32_t XOFF = 2 * STAGEB;
    __nv_bfloat16* H2h = sm + XOFF / 2;
    __nv_bfloat16* H2l = H2h + 128 * HPAD;

    int t = threadIdx.x, lane = t & 31, wid = t >> 5;
    int wm = wid >> 1, wn = wid & 1;
    int m0 = blockIdx.x * 128;
    int rclamp = M - 1 - m0;
    int tgrp = lane >> 3, trow = lane & 7;
    int qrow = lane >> 2, qcol = (lane & 3) * 2;

    float acc[2][8][4];
#pragma unroll
    for (int i = 0; i < 2; i++)
#pragma unroll
        for (int j = 0; j < 8; j++)
#pragma unroll
            for (int k = 0; k < 4; k++) acc[i][j][k] = 0.f;

    const __nv_bfloat16* a0h = g_aggh + (size_t)m0 * HDIM;
    const __nv_bfloat16* a0l = g_aggl + (size_t)m0 * HDIM;
    const __nv_bfloat16* a1h = g_h1h + (size_t)m0 * HDIM;
    const __nv_bfloat16* a1l = g_h1l + (size_t)m0 * HDIM;

    // ---- phase A: h2 = relu([agg|h1] @ [Wl2|Wr2]^T + b2) ----
    issue_tile(sb + XOFF, sb + XOFF + TILEB, a0h, a0l, HDIM, rclamp, 0, t);
    issue_tile(sb, sb + TILEB, g_Wh + 32768, g_Wlo + 32768, 256, 127, 0, t);
    CP_COMMIT();
    for (int ch = 0; ch < 8; ch++) {
        int cur = ch & 1, nxt = (ch + 1) & 1;
        if (ch + 1 < 8) {
            int nc = ch + 1;
            const __nv_bfloat16* sh = (nc < 4) ? a0h : a1h;
            const __nv_bfloat16* sl = (nc < 4) ? a0l : a1l;
            issue_tile(sb + XOFF + nxt * STAGEB, sb + XOFF + nxt * STAGEB + TILEB,
                       sh, sl, HDIM, rclamp, (nc & 3) * 32, t);
            issue_tile(sb + nxt * STAGEB, sb + nxt * STAGEB + TILEB,
                       g_Wh + 32768, g_Wlo + 32768, 256, 127, nc * 32, t);
        }
        CP_COMMIT();
        CP_WAIT1();
        __syncthreads();
        mma_step(sm + (XOFF + cur * STAGEB) / 2, sm + (XOFF + cur * STAGEB + TILEB) / 2,
                 APAD, 0,
                 sm + (cur * STAGEB) / 2, sm + (cur * STAGEB + TILEB) / 2,
                 wm, wn, tgrp, trow, acc);
        __syncthreads();
    }
    // write h2 (bias+relu) into smem as bf16 hi/lo (overwrites phase-A A stages)
#pragma unroll
    for (int mf = 0; mf < 2; mf++)
#pragma unroll
        for (int nf = 0; nf < 8; nf++) {
            int n = wn * 64 + nf * 8 + qcol;
            float bx = __ldg(b2 + n), by = __ldg(b2 + n + 1);
#pragma unroll
            for (int half = 0; half < 2; half++) {
                int row = wm * 32 + mf * 16 + half * 8 + qrow;
                float v0 = fmaxf(acc[mf][nf][half * 2]     + bx, 0.f);
                float v1 = fmaxf(acc[mf][nf][half * 2 + 1] + by, 0.f);
                __nv_bfloat16 h0, l0, h1b, l1b;
                split_bf16(v0, h0, l0);
                split_bf16(v1, h1b, l1b);
                H2h[row * HPAD + n]     = h0;
                H2h[row * HPAD + n + 1] = h1b;
                H2l[row * HPAD + n]     = l0;
                H2l[row * HPAD + n + 1] = l1b;
            }
        }
    __syncthreads();

    // ---- phase B: U[:, y*128..] = h2 @ W3y^T, 8 B-rounds (y = r>>2) ----
    issue_tile(sb, sb + TILEB, g_Wh + 65536, g_Wlo + 65536, 128, 127, 0, t);
    CP_COMMIT();
    for (int r = 0; r < 8; r++) {
        int cur = r & 1, nxt = (r + 1) & 1;
        if ((r & 3) == 0) {
#pragma unroll
            for (int i = 0; i < 2; i++)
#pragma unroll
                for (int j = 0; j < 8; j++)
#pragma unroll
                    for (int k = 0; k < 4; k++) acc[i][j][k] = 0.f;
        }
        if (r + 1 < 8) {
            int nr = r + 1;
            issue_tile(sb + nxt * STAGEB, sb + nxt * STAGEB + TILEB,
                       g_Wh + 65536 + (nr >> 2) * 16384, g_Wlo + 65536 + (nr >> 2) * 16384,
                       128, 127, (nr & 3) * 32, t);
        }
        CP_COMMIT();
        CP_WAIT1();
        __syncthreads();
        mma_step(H2h, H2l, HPAD, (r & 3) * 32,
                 sm + (cur * STAGEB) / 2, sm + (cur * STAGEB + TILEB) / 2,
                 wm, wn, tgrp, trow, acc);
        __syncthreads();
        if ((r & 3) == 3) {
            int y = r >> 2;
#pragma unroll
            for (int mf = 0; mf < 2; mf++)
#pragma unroll
                for (int nf = 0; nf < 8; nf++) {
                    int n = wn * 64 + nf * 8 + qcol;
#pragma unroll
                    for (int half = 0; half < 2; half++) {
                        int gr = m0 + wm * 32 + mf * 16 + half * 8 + qrow;
                        if (gr < M) {
                            *(float2*)(g_U + (size_t)gr * 256 + y * 128 + n) =
                                make_float2(acc[mf][nf][half * 2], acc[mf][nf][half * 2 + 1]);
                        }
                    }
                }
        }
    }
}

// ---------------- pair head: sigmoid(W4 . relu(Ua[a]+Ub[b]+b3) + b4) ----------------
__global__ void __launch_bounds__(256)
pair_kernel(const int* __restrict__ pairs,
            const float* __restrict__ b3, const float* __restrict__ W4,
            const float* __restrict__ b4, float* __restrict__ out, int P) {
    int w    = (blockIdx.x * blockDim.x + threadIdx.x) >> 5;
    int lane = threadIdx.x & 31;
    if (w >= P) return;
    int na = __ldg(&pairs[2 * w]);
    int nb = __ldg(&pairs[2 * w + 1]);
    float4 ua = *((const float4*)(g_U + (size_t)na * 256) + lane);
    float4 ub = *((const float4*)(g_U + (size_t)nb * 256 + 128) + lane);
    float4 bv = *((const float4*)b3 + lane);
    float4 wv = *((const float4*)W4 + lane);
    float s = fmaxf(ua.x + ub.x + bv.x, 0.f) * wv.x
            + fmaxf(ua.y + ub.y + bv.y, 0.f) * wv.y
            + fmaxf(ua.z + ub.z + bv.z, 0.f) * wv.z
            + fmaxf(ua.w + ub.w + bv.w, 0.f) * wv.w;
#pragma unroll
    for (int o = 16; o > 0; o >>= 1)
        s += __shfl_xor_sync(0xffffffffu, s, o);
    if (lane == 0) out[w] = 1.0f / (1.0f + __expf(-(s + b4[0])));
}

// ---------------- launch ----------------
extern "C" void kernel_launch(void* const* d_in, const int* in_sizes, int n_in,
                              void* d_out, int out_size) {
    const float* x    = (const float*)d_in[0];
    const int*   edge = (const int*)d_in[1];
    const int*   prs  = (const int*)d_in[2];
    const float* Wl1  = (const float*)d_in[3];
    const float* Wr1  = (const float*)d_in[4];
    const float* b1   = (const float*)d_in[5];
    const float* Wl2  = (const float*)d_in[6];
    const float* Wr2  = (const float*)d_in[7];
    const float* b2   = (const float*)d_in[8];
    const float* W3   = (const float*)d_in[9];
    const float* b3   = (const float*)d_in[10];
    const float* W4   = (const float*)d_in[11];
    const float* b4   = (const float*)d_in[12];
    float* out = (float*)d_out;

    const int E = in_sizes[1] / 2;
    const int P = in_sizes[2] / 2;
    const int M = N_NODES;
    const int* src = edge;
    const int* dst = edge + E;

    float* g_h1_p;  cudaGetSymbolAddress((void**)&g_h1_p, g_h1);
    int*   g_deg_p; cudaGetSymbolAddress((void**)&g_deg_p, g_deg);

    cudaFuncSetAttribute(tgemm_kernel,   cudaFuncAttributeMaxDynamicSharedMemorySize, T1_SMEM);
    cudaFuncSetAttribute(layer2u_kernel, cudaFuncAttributeMaxDynamicSharedMemorySize, L2U_SMEM);

    // weight split + CSR build
    split_w_kernel<<<(98304 + 255) / 256, 256>>>(Wl1, Wr1, Wl2, Wr2, W3);
    cudaMemsetAsync(g_deg_p, 0, N_NODES * sizeof(int));
    count_deg_kernel<<<(E + 255) / 256, 256>>>(dst, E);
    scan_deg_kernel<<<1, 1024>>>(E);
    fill_csr_kernel<<<(E + 255) / 256, 256>>>(src, dst, E);

    const int mTiles = (M + 127) / 128;   // 391

    // Layer 1
    agg_mean_kernel<<<AGG_BLOCKS, 256>>>(x, 0);
    tgemm_kernel<<<mTiles, 256, T1_SMEM>>>(x, b1, g_h1_p, M);
    // Layer 2 + U fused (h2 never leaves smem)
    agg_mean_kernel<<<AGG_BLOCKS, 256>>>(x, 1);
    layer2u_kernel<<<mTiles, 256, L2U_SMEM>>>(b2, M);
    // Pair head
    pair_kernel<<<(P * 32 + 255) / 256, 256>>>(prs, b3, W4, b4, out, P);
}